// round 8
// baseline (speedup 1.0000x reference)
#include <cuda_runtime.h>
#include <cuda_fp16.h>
#include <cstdint>
#include <math.h>

typedef unsigned int U32;
typedef unsigned long long ULL;

#define B_    32
#define D_    64
#define K_    26
#define QST_  256
#define H_    512
#define NANS  28

// ---- pair-kernel SMEM map (bytes) ----
#define AOFF      0          // A: 128 rows x 512 fp16, row stride 1024B, XOR swizzle (128KB)
#define WOFF      131072     // 3 stages x 32KB weight chunks (hi 16KB + lo 16KB each)
#define BIASOFF   229376     // 512 floats
#define SMEM_PAIR 231424

// ---- device scratch ----
__device__ float  g_u[B_ * D_ * H_];
__device__ float  g_v[B_ * D_ * H_];
__device__ float  g_part[B_ * D_ * H_];
// weights, ldmatrix-ready: [l(3)][kc(32, k16 each)][term(2: hi,lo)] blocks of 16KB
// block = 512 n-rows x 32B (2x16B k-halves), XOR-swizzled for conflict-free LDSM
__device__ __half g_Wh[3 * 32 * 2 * 8192];

// =====================================================================
// helpers
// =====================================================================
__device__ __forceinline__ U32 smem_u32(const void* p) {
    U32 a;
    asm("{ .reg .u64 t; cvta.to.shared.u64 t, %1; cvt.u32.u64 %0, t; }" : "=r"(a) : "l"(p));
    return a;
}
__device__ __forceinline__ void cpasync16(U32 smem, const void* g) {
    asm volatile("cp.async.cg.shared.global [%0], [%1], 16;" :: "r"(smem), "l"(g));
}
#define CP_COMMIT() asm volatile("cp.async.commit_group;" ::: "memory")
#define CP_WAIT1()  asm volatile("cp.async.wait_group 1;" ::: "memory")
#define CP_WAIT0()  asm volatile("cp.async.wait_group 0;" ::: "memory")

__device__ __forceinline__ void ldm_x4(U32& r0, U32& r1, U32& r2, U32& r3, U32 addr) {
    asm volatile("ldmatrix.sync.aligned.m8n8.x4.shared.b16 {%0,%1,%2,%3}, [%4];"
                 : "=r"(r0), "=r"(r1), "=r"(r2), "=r"(r3) : "r"(addr));
}
__device__ __forceinline__ void mma16816(float& d0, float& d1, float& d2, float& d3,
                                         U32 a0, U32 a1, U32 a2, U32 a3, U32 b0, U32 b1) {
    asm volatile("mma.sync.aligned.m16n8k16.row.col.f32.f16.f16.f32 "
                 "{%0,%1,%2,%3}, {%4,%5,%6,%7}, {%8,%9}, {%0,%1,%2,%3};"
                 : "+f"(d0), "+f"(d1), "+f"(d2), "+f"(d3)
                 : "r"(a0), "r"(a1), "r"(a2), "r"(a3), "r"(b0), "r"(b1));
}
__device__ __forceinline__ U32 pack_h2(float a, float b) {
    return (U32)__half_as_ushort(__float2half_rn(a)) |
           ((U32)__half_as_ushort(__float2half_rn(b)) << 16);
}
// A-tile address: row stride 1024B, XOR bits[4:6] with (row&7)<<4
__device__ __forceinline__ U32 a_addr(U32 smem, int row, U32 colbyte) {
    return smem + AOFF + (U32)row * 1024u + (colbyte ^ (U32)((row & 7) << 4));
}
__device__ __forceinline__ void stsh32(U32 addr, U32 v) {
    asm volatile("st.shared.b32 [%0], %1;" :: "r"(addr), "r"(v) : "memory");
}

// =====================================================================
// Prep 1: per-object projections u, v (folds layer 0: 64x cheaper)
// =====================================================================
__global__ void prep_uv(const float* __restrict__ x,
                        const float* __restrict__ W0,
                        const float* __restrict__ b0) {
    extern __shared__ float smf[];
    float* Ws = smf;
    float* xs = smf + H_ * 52;
    int b = blockIdx.x, tid = threadIdx.x;
    for (int i = tid; i < H_ * 52; i += blockDim.x) Ws[i] = W0[i];
    for (int i = tid; i < D_ * K_; i += blockDim.x) xs[i] = x[b * D_ * K_ + i];
    __syncthreads();
    float bb = b0[tid];
    const float* w = Ws + tid * 52;
    for (int o = 0; o < D_; ++o) {
        const float* xo = xs + o * K_;
        float u = 0.f, v = 0.f;
#pragma unroll
        for (int j = 0; j < K_; ++j) {
            u = fmaf(w[j],      xo[j], u);
            v = fmaf(w[26 + j], xo[j], v);
        }
        g_u[(b * D_ + o) * H_ + tid] = u;
        g_v[(b * D_ + o) * H_ + tid] = v + bb;
    }
}

// =====================================================================
// Prep 2: split W1..W3 into fp16 hi/lo, ldmatrix-ready swizzled blocks.
// element (l, n, k): kc = k>>4, kk = k&15
// byte in block = ((n*32 + (kk>>3)*16) ^ (((n>>2)&1)<<4)) + (kk&7)*2
// =====================================================================
__global__ void prep_w(const float* __restrict__ W1,
                       const float* __restrict__ W2,
                       const float* __restrict__ W3) {
    int idx = blockIdx.x * blockDim.x + threadIdx.x;
    if (idx >= 3 * H_ * H_) return;
    int l = idx / (H_ * H_);
    int rem = idx - l * H_ * H_;
    int n = rem >> 9, k = rem & 511;
    const float* W = (l == 0) ? W1 : ((l == 1) ? W2 : W3);
    float w = W[n * H_ + k];
    __half hi = __float2half_rn(w);
    __half lo = __float2half_rn(w - __half2float(hi));
    int kc = k >> 4, kk = k & 15;
    U32 inner = ((U32)(n * 32 + ((kk >> 3) << 4)) ^ (U32)(((n >> 2) & 1) << 4)) + (U32)((kk & 7) * 2);
    char* base = (char*)g_Wh + ((size_t)(l * 32 + kc) * 2) * 16384;
    *(__half*)(base + inner)         = hi;   // term 0 = hi
    *(__half*)(base + 16384 + inner) = lo;   // term 1 = lo
}

// =====================================================================
// Main pair kernel: HMMA fused layer0 + 3x(512x512) + aggregation.
// grid = (32, 32): p0 = 2*blockIdx.x, b = blockIdx.y. 512 threads.
// Warp tile m16 x n256 (acc = 128 f32 regs). 32 k-chunks of 16, 3-stage
// cp.async ring, single barrier per chunk, 2-chunk prefetch lookahead.
// =====================================================================
__global__ __launch_bounds__(512, 1)
void rn_pair_kernel(const float* __restrict__ b1,
                    const float* __restrict__ b2,
                    const float* __restrict__ b3) {
    extern __shared__ __align__(16) char smc[];
    const U32 smem = smem_u32(smc);
    float* bsm = (float*)(smc + BIASOFF);
    const int tid = threadIdx.x;
    const int wid = tid >> 5, lane = tid & 31;
    const int rg = wid & 7, cg = wid >> 3;          // 8 row groups x 2 col groups
    const int b = blockIdx.y;
    const int p0 = blockIdx.x * 2;

    // ---- layer 0 fill: A[r][c] = fp16(relu(u[b, r&63, c] + v[b, p0+(r>>6), c])) ----
    {
        const int r = tid >> 2, qd = tid & 3;
        const int q = r & 63, p = p0 + (r >> 6);
        const float4* u4 = (const float4*)(g_u + (size_t)(b * D_ + q) * H_);
        const float4* v4 = (const float4*)(g_v + (size_t)(b * D_ + p) * H_);
#pragma unroll 4
        for (int it = 0; it < 16; ++it) {
            int c4 = qd * 32 + it * 2;
            float4 ua = u4[c4], ub = u4[c4 + 1], va = v4[c4], vb = v4[c4 + 1];
            float t0 = fmaxf(ua.x + va.x, 0.f), t1 = fmaxf(ua.y + va.y, 0.f);
            float t2 = fmaxf(ua.z + va.z, 0.f), t3 = fmaxf(ua.w + va.w, 0.f);
            float t4 = fmaxf(ub.x + vb.x, 0.f), t5 = fmaxf(ub.y + vb.y, 0.f);
            float t6 = fmaxf(ub.z + vb.z, 0.f), t7 = fmaxf(ub.w + vb.w, 0.f);
            U32 p0w = pack_h2(t0, t1), p1w = pack_h2(t2, t3);
            U32 p2w = pack_h2(t4, t5), p3w = pack_h2(t6, t7);
            U32 addr = a_addr(smem, r, (U32)(qd * 256 + it * 16));
            asm volatile("st.shared.v4.b32 [%0], {%1,%2,%3,%4};"
                         :: "r"(addr), "r"(p0w), "r"(p1w), "r"(p2w), "r"(p3w) : "memory");
        }
    }

    // per-thread invariant ldmatrix address parts
    const int arow = rg * 16 + (lane & 15);                 // A frag row for this lane
    const U32 arsw = (U32)((arow & 7) << 4);
    const U32 arbase = smem + AOFF + (U32)arow * 1024u;
    const U32 al16 = (U32)(lane & 16);                      // +16B for k+8 halves
    const int bd = (lane & 7) + ((lane & 16) >> 1);         // B n-row within 16-row group
    const U32 bT = (U32)(cg * 8192) +                       // col-group: 256-row half
                   (U32)((bd * 32 + (((lane >> 3) & 1) << 4)) ^ (((bd >> 2) & 1) << 4));

    // stage loader: chunk (l, it) -> ring buffer buf
    auto load_stage = [&](int l, int it, int buf) {
        const char* src = (const char*)g_Wh + ((size_t)(l * 32 + it) * 2) * 16384 + tid * 16;
        U32 d = smem + WOFF + (U32)buf * 32768 + (U32)tid * 16;
#pragma unroll
        for (int j = 0; j < 4; ++j)
            cpasync16(d + (U32)j * 8192, src + (size_t)j * 8192);
        CP_COMMIT();
    };

    // prologue: first two chunks of layer 0
    load_stage(0, 0, 0);
    load_stage(0, 1, 1);

    for (int l = 0; l < 3; ++l) {
        const float* bias = (l == 0) ? b1 : ((l == 1) ? b2 : b3);
        bsm[tid] = bias[tid];     // ordered vs epilogue reads by in-loop barriers

        float acc[32][4];
#pragma unroll
        for (int f = 0; f < 32; ++f) {
            acc[f][0] = 0.f; acc[f][1] = 0.f; acc[f][2] = 0.f; acc[f][3] = 0.f;
        }

        for (int i = 0; i < 32; ++i) {
            if (i + 1 < 32) CP_WAIT1(); else CP_WAIT0();   // my copies of chunk i done
            __syncthreads();                                // all copies visible; compute(i-1) done
            if (i + 2 < 32) load_stage(l, i + 2, (i + 2) % 3);  // buf (i-1)%3, free by barrier

            // A fragment for k window i (shared by hi and lo terms)
            U32 a0, a1, a2, a3;
            ldm_x4(a0, a1, a2, a3, arbase + (((U32)(i * 32) + al16) ^ arsw));

            const U32 wb = smem + WOFF + (U32)(i % 3) * 32768;
#pragma unroll
            for (int t = 0; t < 2; ++t) {
                const U32 bb = wb + (U32)(t * 16384) + bT;
#pragma unroll
                for (int nf2 = 0; nf2 < 16; ++nf2) {
                    U32 b0, b1, b2c, b3c;
                    ldm_x4(b0, b1, b2c, b3c, bb + (U32)(nf2 * 512));
                    mma16816(acc[2*nf2][0], acc[2*nf2][1], acc[2*nf2][2], acc[2*nf2][3],
                             a0, a1, a2, a3, b0, b1);
                    mma16816(acc[2*nf2+1][0], acc[2*nf2+1][1], acc[2*nf2+1][2], acc[2*nf2+1][3],
                             a0, a1, a2, a3, b2c, b3c);
                }
            }
        }
        __syncthreads();          // all A reads done; ring fully drained

        // prefetch next layer's first two chunks behind the epilogue
        if (l + 1 < 3) {
            load_stage(l + 1, 0, 0);
            load_stage(l + 1, 1, 1);
        }

        // ---- epilogue: +bias, relu, pack fp16, write A in place ----
        {
            const int rA = rg * 16 + (lane >> 2);
#pragma unroll
            for (int f = 0; f < 32; ++f) {
                int nc = cg * 256 + f * 8 + ((lane & 3) << 1);
                float bx = bsm[nc], by = bsm[nc + 1];
                U32 lo = pack_h2(fmaxf(acc[f][0] + bx, 0.f), fmaxf(acc[f][1] + by, 0.f));
                U32 hi = pack_h2(fmaxf(acc[f][2] + bx, 0.f), fmaxf(acc[f][3] + by, 0.f));
                stsh32(a_addr(smem, rA,     (U32)(nc * 2)), lo);
                stsh32(a_addr(smem, rA + 8, (U32)(nc * 2)), hi);
            }
        }
        __syncthreads();          // A complete before next layer / aggregation
    }

    // ---- deterministic aggregation: per (p-half, col-pair) sums over 64 rows ----
    {
        const int g = tid >> 8, c2 = (tid & 255) * 2;
        float s0 = 0.f, s1 = 0.f;
#pragma unroll 8
        for (int rr = 0; rr < 64; ++rr) {
            int r = g * 64 + rr;
            U32 h2;
            asm volatile("ld.shared.b32 %0, [%1];" : "=r"(h2)
                         : "r"(a_addr(smem, r, (U32)(c2 * 2))));
            s0 += __half2float(__ushort_as_half((unsigned short)(h2 & 0xffff)));
            s1 += __half2float(__ushort_as_half((unsigned short)(h2 >> 16)));
        }
        g_part[((size_t)b * D_ + p0 + g) * H_ + c2]     = s0;
        g_part[((size_t)b * D_ + p0 + g) * H_ + c2 + 1] = s1;
    }
}

// =====================================================================
// Head: reduce partials, concat qst, layers 4-6, log_softmax.
// grid = 32, block = 1024 (32 warps, float4 warp-dots).
// =====================================================================
__global__ __launch_bounds__(1024)
void rn_head_kernel(const float* __restrict__ qst,
                    const float* __restrict__ W4, const float* __restrict__ b4,
                    const float* __restrict__ W5, const float* __restrict__ b5,
                    const float* __restrict__ W6, const float* __restrict__ b6,
                    float* __restrict__ out) {
    __shared__ float red[1024];
    __shared__ __align__(16) float hin[H_ + QST_];
    __shared__ __align__(16) float h4[H_];
    __shared__ __align__(16) float h5[H_];
    __shared__ float logits[NANS];
    const int b = blockIdx.x, tid = threadIdx.x;
    const int w = tid >> 5, lane = tid & 31;

    {
        const int c = tid & 511, hh = tid >> 9;
        const float* pp = g_part + ((size_t)b * D_ + hh * 32) * H_ + c;
        float s = 0.f;
#pragma unroll 8
        for (int r = 0; r < 32; ++r) s += pp[r * H_];
        red[tid] = s;
    }
    __syncthreads();
    if (tid < H_) hin[tid] = red[tid] + red[tid + 512];
    else if (tid < H_ + QST_) hin[tid] = qst[b * QST_ + (tid - H_)];
    __syncthreads();

    for (int k = 0; k < 16; ++k) {                        // layer 4: 768 -> 512
        const int o = w * 16 + k;
        const float4* wr = (const float4*)(W4 + (size_t)o * (H_ + QST_));
        const float4* hv = (const float4*)hin;
        float a = 0.f;
#pragma unroll
        for (int m = 0; m < 6; ++m) {
            float4 x4 = wr[lane + 32 * m], y4 = hv[lane + 32 * m];
            a += x4.x * y4.x + x4.y * y4.y + x4.z * y4.z + x4.w * y4.w;
        }
#pragma unroll
        for (int off = 16; off; off >>= 1) a += __shfl_xor_sync(0xffffffffu, a, off);
        if (lane == 0) { float t = a + b4[o]; h4[o] = t > 0.f ? t : 0.f; }
    }
    __syncthreads();

    for (int k = 0; k < 16; ++k) {                        // layer 5: 512 -> 512
        const int o = w * 16 + k;
        const float4* wr = (const float4*)(W5 + (size_t)o * H_);
        const float4* hv = (const float4*)h4;
        float a = 0.f;
#pragma unroll
        for (int m = 0; m < 4; ++m) {
            float4 x4 = wr[lane + 32 * m], y4 = hv[lane + 32 * m];
            a += x4.x * y4.x + x4.y * y4.y + x4.z * y4.z + x4.w * y4.w;
        }
#pragma unroll
        for (int off = 16; off; off >>= 1) a += __shfl_xor_sync(0xffffffffu, a, off);
        if (lane == 0) { float t = a + b5[o]; h5[o] = t > 0.f ? t : 0.f; }
    }
    __syncthreads();

    if (w < NANS) {                                       // layer 6: 512 -> 28
        const float4* wr = (const float4*)(W6 + (size_t)w * H_);
        const float4* hv = (const float4*)h5;
        float a = 0.f;
#pragma unroll
        for (int m = 0; m < 4; ++m) {
            float4 x4 = wr[lane + 32 * m], y4 = hv[lane + 32 * m];
            a += x4.x * y4.x + x4.y * y4.y + x4.z * y4.z + x4.w * y4.w;
        }
#pragma unroll
        for (int off = 16; off; off >>= 1) a += __shfl_xor_sync(0xffffffffu, a, off);
        if (lane == 0) logits[w] = a + b6[w];
    }
    __syncthreads();

    if (w == 0) {
        float z = lane < NANS ? logits[lane] : -INFINITY;
        float m = z;
#pragma unroll
        for (int off = 16; off; off >>= 1) m = fmaxf(m, __shfl_xor_sync(0xffffffffu, m, off));
        float e = lane < NANS ? expf(z - m) : 0.f;
        float s = e;
#pragma unroll
        for (int off = 16; off; off >>= 1) s += __shfl_xor_sync(0xffffffffu, s, off);
        if (lane < NANS) out[b * NANS + lane] = z - m - logf(s);
    }
}

// =====================================================================
extern "C" void kernel_launch(void* const* d_in, const int* in_sizes, int n_in,
                              void* d_out, int out_size) {
    const float* x   = (const float*)d_in[0];
    const float* qst = (const float*)d_in[1];
    const float* W0  = (const float*)d_in[2];
    const float* b0  = (const float*)d_in[3];
    const float* W1  = (const float*)d_in[4];
    const float* b1  = (const float*)d_in[5];
    const float* W2  = (const float*)d_in[6];
    const float* b2  = (const float*)d_in[7];
    const float* W3  = (const float*)d_in[8];
    const float* b3  = (const float*)d_in[9];
    const float* W4  = (const float*)d_in[10];
    const float* b4  = (const float*)d_in[11];
    const float* W5  = (const float*)d_in[12];
    const float* b5  = (const float*)d_in[13];
    const float* W6  = (const float*)d_in[14];
    const float* b6  = (const float*)d_in[15];
    float* out = (float*)d_out;

    const int smem_uv = (H_ * 52 + D_ * K_) * 4;
    cudaFuncSetAttribute(prep_uv,        cudaFuncAttributeMaxDynamicSharedMemorySize, smem_uv);
    cudaFuncSetAttribute(rn_pair_kernel, cudaFuncAttributeMaxDynamicSharedMemorySize, SMEM_PAIR);

    prep_uv<<<B_, 512, smem_uv>>>(x, W0, b0);
    prep_w<<<(3 * H_ * H_ + 255) / 256, 256>>>(W1, W2, W3);
    rn_pair_kernel<<<dim3(D_ / 2, B_), 512, SMEM_PAIR>>>(b1, b2, b3);
    rn_head_kernel<<<B_, 1024>>>(qst, W4, b4, W5, b5, W6, b6, out);
}

// round 10
// speedup vs baseline: 2.2872x; 2.2872x over previous
#include <cuda_runtime.h>
#include <cuda_fp16.h>
#include <cstdint>
#include <math.h>

typedef unsigned int U32;
typedef unsigned long long ULL;

#define B_    32
#define D_    64
#define K_    26
#define QST_  256
#define H_    512
#define NANS  28

// ---- pair-kernel SMEM map (bytes) ----
#define AOFF      0          // A: 128 rows x 512 fp16, row stride 1024B, XOR swizzle (128KB)
#define WOFF      131072     // 3-stage ring x 32KB weight chunks
#define BIASOFF   229376     // 512 floats
#define SMEM_PAIR 231424

// ---- device scratch ----
__device__ float  g_u[B_ * D_ * H_];
__device__ float  g_v[B_ * D_ * H_];
__device__ float  g_part[B_ * D_ * H_];
// weights, ldmatrix-ready: chunk g = (l*2+nch)*16+kc, 32KB each:
// [term(2)][ks(2)] blocks of 8KB = 256 n-rows x 32B, XOR-swizzled
__device__ __half g_Wh[3 * 2 * 16 * 2 * 2 * 4096];
// chunk-0 activation stash: [cta(1024)][tid(512)][8 x uint4]
__device__ uint4  g_stash[1024 * 512 * 8];

// =====================================================================
// helpers
// =====================================================================
__device__ __forceinline__ U32 smem_u32(const void* p) {
    U32 a;
    asm("{ .reg .u64 t; cvta.to.shared.u64 t, %1; cvt.u32.u64 %0, t; }" : "=r"(a) : "l"(p));
    return a;
}
__device__ __forceinline__ void cpasync16(U32 smem, const void* g) {
    asm volatile("cp.async.cg.shared.global [%0], [%1], 16;" :: "r"(smem), "l"(g));
}
#define CP_COMMIT() asm volatile("cp.async.commit_group;" ::: "memory")
#define CP_WAIT1()  asm volatile("cp.async.wait_group 1;" ::: "memory")
#define CP_WAIT0()  asm volatile("cp.async.wait_group 0;" ::: "memory")

__device__ __forceinline__ void ldm_x4(U32& r0, U32& r1, U32& r2, U32& r3, U32 addr) {
    asm volatile("ldmatrix.sync.aligned.m8n8.x4.shared.b16 {%0,%1,%2,%3}, [%4];"
                 : "=r"(r0), "=r"(r1), "=r"(r2), "=r"(r3) : "r"(addr));
}
__device__ __forceinline__ void mma16816(float& d0, float& d1, float& d2, float& d3,
                                         U32 a0, U32 a1, U32 a2, U32 a3, U32 b0, U32 b1) {
    asm volatile("mma.sync.aligned.m16n8k16.row.col.f32.f16.f16.f32 "
                 "{%0,%1,%2,%3}, {%4,%5,%6,%7}, {%8,%9}, {%0,%1,%2,%3};"
                 : "+f"(d0), "+f"(d1), "+f"(d2), "+f"(d3)
                 : "r"(a0), "r"(a1), "r"(a2), "r"(a3), "r"(b0), "r"(b1));
}
__device__ __forceinline__ U32 pack_h2(float a, float b) {
    return (U32)__half_as_ushort(__float2half_rn(a)) |
           ((U32)__half_as_ushort(__float2half_rn(b)) << 16);
}
// A-tile address: row stride 1024B, XOR bits[4:6] with (row&7)<<4
__device__ __forceinline__ U32 a_addr(U32 smem, int row, U32 colbyte) {
    return smem + AOFF + (U32)row * 1024u + (colbyte ^ (U32)((row & 7) << 4));
}
__device__ __forceinline__ void stsh32(U32 addr, U32 v) {
    asm volatile("st.shared.b32 [%0], %1;" :: "r"(addr), "r"(v) : "memory");
}

// =====================================================================
// Prep 1: per-object projections u, v (folds layer 0: 64x cheaper)
// =====================================================================
__global__ void prep_uv(const float* __restrict__ x,
                        const float* __restrict__ W0,
                        const float* __restrict__ b0) {
    extern __shared__ float smf[];
    float* Ws = smf;
    float* xs = smf + H_ * 52;
    int b = blockIdx.x, tid = threadIdx.x;
    for (int i = tid; i < H_ * 52; i += blockDim.x) Ws[i] = W0[i];
    for (int i = tid; i < D_ * K_; i += blockDim.x) xs[i] = x[b * D_ * K_ + i];
    __syncthreads();
    float bb = b0[tid];
    const float* w = Ws + tid * 52;
    for (int o = 0; o < D_; ++o) {
        const float* xo = xs + o * K_;
        float u = 0.f, v = 0.f;
#pragma unroll
        for (int j = 0; j < K_; ++j) {
            u = fmaf(w[j],      xo[j], u);
            v = fmaf(w[26 + j], xo[j], v);
        }
        g_u[(b * D_ + o) * H_ + tid] = u;
        g_v[(b * D_ + o) * H_ + tid] = v + bb;
    }
}

// =====================================================================
// Prep 2: split W1..W3 into fp16 hi/lo, ldmatrix-ready swizzled blocks.
// chunk g = (l*2+nch)*16+kc (32KB): [term(2)][ks(2)] 8KB blocks of
// 256 n-rows x 32B; byte = ((nr*32 + kpart*16) ^ (((nr>>2)&1)<<4)) + (kk&7)*2
// =====================================================================
__global__ void prep_w(const float* __restrict__ W1,
                       const float* __restrict__ W2,
                       const float* __restrict__ W3) {
    int idx = blockIdx.x * blockDim.x + threadIdx.x;
    if (idx >= 3 * H_ * H_) return;
    int l = idx / (H_ * H_);
    int rem = idx - l * H_ * H_;
    int n = rem >> 9, k = rem & 511;
    const float* W = (l == 0) ? W1 : ((l == 1) ? W2 : W3);
    float w = W[n * H_ + k];
    __half hi = __float2half_rn(w);
    __half lo = __float2half_rn(w - __half2float(hi));
    int nch = n >> 8, nr = n & 255;
    int kc = k >> 5, ks = (k >> 4) & 1, kk = k & 15;
    U32 inner = (U32)((nr * 32 + ((kk >> 3) << 4)) ^ (((nr >> 2) & 1) << 4)) + (U32)((kk & 7) * 2);
    char* base = (char*)g_Wh + (size_t)((l * 2 + nch) * 16 + kc) * 32768;
    *(__half*)(base + (size_t)(0 * 2 + ks) * 8192 + inner) = hi;
    *(__half*)(base + (size_t)(1 * 2 + ks) * 8192 + inner) = lo;
}

// =====================================================================
// Main pair kernel: HMMA fused layer0 + 3x(512x512) + aggregation.
// grid = (32, 32): p0 = 2*blockIdx.x, b = blockIdx.y. 512 threads.
// Two N-passes (n256) per layer, acc = 64 regs. 96-chunk global stream
// through a 3-stage ring, one barrier per chunk, 2-chunk lookahead.
// =====================================================================
__global__ __launch_bounds__(512, 1)
void rn_pair_kernel(const float* __restrict__ b1,
                    const float* __restrict__ b2,
                    const float* __restrict__ b3) {
    extern __shared__ __align__(16) char smc[];
    const U32 smem = smem_u32(smc);
    float* bsm = (float*)(smc + BIASOFF);
    const int tid = threadIdx.x;
    const int wid = tid >> 5, lane = tid & 31;
    const int rg = wid & 7, cg = wid >> 3;          // 8 row groups x 2 col groups
    const int b = blockIdx.y;
    const int p0 = blockIdx.x * 2;
    const int cta = b * 32 + blockIdx.x;

    // ---- layer 0 fill: A[r][c] = fp16(relu(u[b, r&63, c] + v[b, p0+(r>>6), c])) ----
    {
        const int r = tid >> 2, qd = tid & 3;
        const int q = r & 63, p = p0 + (r >> 6);
        const float4* u4 = (const float4*)(g_u + (size_t)(b * D_ + q) * H_);
        const float4* v4 = (const float4*)(g_v + (size_t)(b * D_ + p) * H_);
#pragma unroll 4
        for (int it = 0; it < 16; ++it) {
            int c4 = qd * 32 + it * 2;
            float4 ua = u4[c4], ub = u4[c4 + 1], va = v4[c4], vb = v4[c4 + 1];
            float t0 = fmaxf(ua.x + va.x, 0.f), t1 = fmaxf(ua.y + va.y, 0.f);
            float t2 = fmaxf(ua.z + va.z, 0.f), t3 = fmaxf(ua.w + va.w, 0.f);
            float t4 = fmaxf(ub.x + vb.x, 0.f), t5 = fmaxf(ub.y + vb.y, 0.f);
            float t6 = fmaxf(ub.z + vb.z, 0.f), t7 = fmaxf(ub.w + vb.w, 0.f);
            U32 p0w = pack_h2(t0, t1), p1w = pack_h2(t2, t3);
            U32 p2w = pack_h2(t4, t5), p3w = pack_h2(t6, t7);
            U32 addr = a_addr(smem, r, (U32)(qd * 256 + it * 16));
            asm volatile("st.shared.v4.b32 [%0], {%1,%2,%3,%4};"
                         :: "r"(addr), "r"(p0w), "r"(p1w), "r"(p2w), "r"(p3w) : "memory");
        }
    }

    // per-thread invariant ldmatrix address parts
    const int arow = rg * 16 + (lane & 15);                 // A frag row for this lane
    const U32 arsw = (U32)((arow & 7) << 4);
    const U32 arbase = smem + AOFF + (U32)arow * 1024u;
    const U32 al16 = (U32)(lane & 16);                      // +16B for k+8 halves
    const int bd = (lane & 7) + ((lane & 16) >> 1);         // B n-row within 16-row group
    const U32 bT = (U32)(cg * 4096) +                       // col-group: 128-row half of 256
                   (U32)((bd * 32 + (((lane >> 3) & 1) << 4)) ^ (((bd >> 2) & 1) << 4));

    // chunk-stream loader: chunk g -> ring buffer g%3
    auto load_stage = [&](int g) {
        const char* src = (const char*)g_Wh + (size_t)g * 32768 + tid * 16;
        U32 d = smem + WOFF + (U32)(g % 3) * 32768 + (U32)tid * 16;
#pragma unroll
        for (int j = 0; j < 4; ++j)
            cpasync16(d + (U32)j * 8192, src + (size_t)j * 8192);
        CP_COMMIT();
    };

    // prologue: first two chunks of the 96-chunk stream
    load_stage(0);
    load_stage(1);

    int g = 0;
    for (int l = 0; l < 3; ++l) {
        const float* bias = (l == 0) ? b1 : ((l == 1) ? b2 : b3);
        bsm[tid] = bias[tid];   // ordered before epilogue reads by in-loop barriers

        for (int nch = 0; nch < 2; ++nch) {
            float acc[16][4];
#pragma unroll
            for (int f = 0; f < 16; ++f) {
                acc[f][0] = 0.f; acc[f][1] = 0.f; acc[f][2] = 0.f; acc[f][3] = 0.f;
            }

            for (int kc = 0; kc < 16; ++kc, ++g) {
                if (g < 95) CP_WAIT1(); else CP_WAIT0();  // chunk g's copies done (mine)
                __syncthreads();                           // all copies visible; compute(g-1) done
                if (g + 2 < 96) load_stage(g + 2);         // buf (g-1)%3, freed by barrier

                const U32 wb = smem + WOFF + (U32)(g % 3) * 32768;
#pragma unroll
                for (int ks = 0; ks < 2; ++ks) {
                    // A fragment (shared between hi and lo terms)
                    U32 cb = (U32)(kc * 64 + ks * 32) + al16;
                    U32 a0, a1, a2, a3;
                    ldm_x4(a0, a1, a2, a3, arbase + (cb ^ arsw));
#pragma unroll
                    for (int t = 0; t < 2; ++t) {
                        const U32 bb = wb + (U32)((t * 2 + ks) * 8192) + bT;
#pragma unroll
                        for (int fp = 0; fp < 8; ++fp) {
                            U32 b0, b1, b2c, b3c;
                            ldm_x4(b0, b1, b2c, b3c, bb + (U32)(fp * 512));
                            mma16816(acc[2*fp][0], acc[2*fp][1], acc[2*fp][2], acc[2*fp][3],
                                     a0, a1, a2, a3, b0, b1);
                            mma16816(acc[2*fp+1][0], acc[2*fp+1][1], acc[2*fp+1][2], acc[2*fp+1][3],
                                     a0, a1, a2, a3, b2c, b3c);
                        }
                    }
                }
            }

            // ---- epilogue: +bias, relu, pack fp16 pairs ----
            U32 pk[32];
#pragma unroll
            for (int f = 0; f < 16; ++f) {
                int nc = nch * 256 + cg * 128 + f * 8 + ((lane & 3) << 1);
                float bx = bsm[nc], by = bsm[nc + 1];
                pk[2 * f]     = pack_h2(fmaxf(acc[f][0] + bx, 0.f), fmaxf(acc[f][1] + by, 0.f));
                pk[2 * f + 1] = pack_h2(fmaxf(acc[f][2] + bx, 0.f), fmaxf(acc[f][3] + by, 0.f));
            }

            if (nch == 0) {
                // stash chunk-0 output per-thread-contiguous in global scratch
                uint4* dst = g_stash + ((size_t)cta * 512 + tid) * 8;
#pragma unroll
                for (int j = 0; j < 8; ++j)
                    dst[j] = make_uint4(pk[4*j], pk[4*j+1], pk[4*j+2], pk[4*j+3]);
                // A still being read next pass: no A writes, no barrier needed here
                // (next pass's chunk barrier orders everything else)
            } else {
                // NOTE: A reads for this layer ended at the last chunk's compute;
                // the barrier inside the NEXT chunk iteration hasn't happened yet,
                // so we need one before overwriting A.
                __syncthreads();
                // chunk-1 -> A[:,256:512]
                const int rA = rg * 16 + (lane >> 2);
#pragma unroll
                for (int f = 0; f < 16; ++f) {
                    int nc = 256 + cg * 128 + f * 8 + ((lane & 3) << 1);
                    stsh32(a_addr(smem, rA,     (U32)(nc * 2)), pk[2*f]);
                    stsh32(a_addr(smem, rA + 8, (U32)(nc * 2)), pk[2*f+1]);
                }
                // chunk-0 stash -> A[:,0:256]  (own data; no fence needed)
                const uint4* src = g_stash + ((size_t)cta * 512 + tid) * 8;
#pragma unroll
                for (int j = 0; j < 8; ++j) {
                    uint4 s = src[j];
                    U32 q0[4] = { s.x, s.y, s.z, s.w };
#pragma unroll
                    for (int c = 0; c < 4; ++c) {
                        int i = j * 4 + c, f = i >> 1, h = i & 1;
                        int nc = cg * 128 + f * 8 + ((lane & 3) << 1);
                        stsh32(a_addr(smem, rA + h * 8, (U32)(nc * 2)), q0[c]);
                    }
                }
                __syncthreads();   // A complete (and bias free) before next layer
            }
        }
    }

    // ---- deterministic aggregation: per (p-half, col-pair) sums over 64 rows ----
    {
        const int gg = tid >> 8, c2 = (tid & 255) * 2;
        float s0 = 0.f, s1 = 0.f;
#pragma unroll 8
        for (int rr = 0; rr < 64; ++rr) {
            int r = gg * 64 + rr;
            U32 h2;
            asm volatile("ld.shared.b32 %0, [%1];" : "=r"(h2)
                         : "r"(a_addr(smem, r, (U32)(c2 * 2))));
            s0 += __half2float(__ushort_as_half((unsigned short)(h2 & 0xffff)));
            s1 += __half2float(__ushort_as_half((unsigned short)(h2 >> 16)));
        }
        g_part[((size_t)b * D_ + p0 + gg) * H_ + c2]     = s0;
        g_part[((size_t)b * D_ + p0 + gg) * H_ + c2 + 1] = s1;
    }
}

// =====================================================================
// Head: reduce partials, concat qst, layers 4-6, log_softmax.
// grid = 32, block = 1024 (32 warps, float4 warp-dots).
// =====================================================================
__global__ __launch_bounds__(1024)
void rn_head_kernel(const float* __restrict__ qst,
                    const float* __restrict__ W4, const float* __restrict__ b4,
                    const float* __restrict__ W5, const float* __restrict__ b5,
                    const float* __restrict__ W6, const float* __restrict__ b6,
                    float* __restrict__ out) {
    __shared__ float red[1024];
    __shared__ __align__(16) float hin[H_ + QST_];
    __shared__ __align__(16) float h4[H_];
    __shared__ __align__(16) float h5[H_];
    __shared__ float logits[NANS];
    const int b = blockIdx.x, tid = threadIdx.x;
    const int w = tid >> 5, lane = tid & 31;

    {
        const int c = tid & 511, hh = tid >> 9;
        const float* pp = g_part + ((size_t)b * D_ + hh * 32) * H_ + c;
        float s = 0.f;
#pragma unroll 8
        for (int r = 0; r < 32; ++r) s += pp[r * H_];
        red[tid] = s;
    }
    __syncthreads();
    if (tid < H_) hin[tid] = red[tid] + red[tid + 512];
    else if (tid < H_ + QST_) hin[tid] = qst[b * QST_ + (tid - H_)];
    __syncthreads();

    for (int k = 0; k < 16; ++k) {                        // layer 4: 768 -> 512
        const int o = w * 16 + k;
        const float4* wr = (const float4*)(W4 + (size_t)o * (H_ + QST_));
        const float4* hv = (const float4*)hin;
        float a = 0.f;
#pragma unroll
        for (int m = 0; m < 6; ++m) {
            float4 x4 = wr[lane + 32 * m], y4 = hv[lane + 32 * m];
            a += x4.x * y4.x + x4.y * y4.y + x4.z * y4.z + x4.w * y4.w;
        }
#pragma unroll
        for (int off = 16; off; off >>= 1) a += __shfl_xor_sync(0xffffffffu, a, off);
        if (lane == 0) { float t = a + b4[o]; h4[o] = t > 0.f ? t : 0.f; }
    }
    __syncthreads();

    for (int k = 0; k < 16; ++k) {                        // layer 5: 512 -> 512
        const int o = w * 16 + k;
        const float4* wr = (const float4*)(W5 + (size_t)o * H_);
        const float4* hv = (const float4*)h4;
        float a = 0.f;
#pragma unroll
        for (int m = 0; m < 4; ++m) {
            float4 x4 = wr[lane + 32 * m], y4 = hv[lane + 32 * m];
            a += x4.x * y4.x + x4.y * y4.y + x4.z * y4.z + x4.w * y4.w;
        }
#pragma unroll
        for (int off = 16; off; off >>= 1) a += __shfl_xor_sync(0xffffffffu, a, off);
        if (lane == 0) { float t = a + b5[o]; h5[o] = t > 0.f ? t : 0.f; }
    }
    __syncthreads();

    if (w < NANS) {                                       // layer 6: 512 -> 28
        const float4* wr = (const float4*)(W6 + (size_t)w * H_);
        const float4* hv = (const float4*)h5;
        float a = 0.f;
#pragma unroll
        for (int m = 0; m < 4; ++m) {
            float4 x4 = wr[lane + 32 * m], y4 = hv[lane + 32 * m];
            a += x4.x * y4.x + x4.y * y4.y + x4.z * y4.z + x4.w * y4.w;
        }
#pragma unroll
        for (int off = 16; off; off >>= 1) a += __shfl_xor_sync(0xffffffffu, a, off);
        if (lane == 0) logits[w] = a + b6[w];
    }
    __syncthreads();

    if (w == 0) {
        float z = lane < NANS ? logits[lane] : -INFINITY;
        float m = z;
#pragma unroll
        for (int off = 16; off; off >>= 1) m = fmaxf(m, __shfl_xor_sync(0xffffffffu, m, off));
        float e = lane < NANS ? expf(z - m) : 0.f;
        float s = e;
#pragma unroll
        for (int off = 16; off; off >>= 1) s += __shfl_xor_sync(0xffffffffu, s, off);
        if (lane < NANS) out[b * NANS + lane] = z - m - logf(s);
    }
}

// =====================================================================
extern "C" void kernel_launch(void* const* d_in, const int* in_sizes, int n_in,
                              void* d_out, int out_size) {
    const float* x   = (const float*)d_in[0];
    const float* qst = (const float*)d_in[1];
    const float* W0  = (const float*)d_in[2];
    const float* b0  = (const float*)d_in[3];
    const float* W1  = (const float*)d_in[4];
    const float* b1  = (const float*)d_in[5];
    const float* W2  = (const float*)d_in[6];
    const float* b2  = (const float*)d_in[7];
    const float* W3  = (const float*)d_in[8];
    const float* b3  = (const float*)d_in[9];
    const float* W4  = (const float*)d_in[10];
    const float* b4  = (const float*)d_in[11];
    const float* W5  = (const float*)d_in[12];
    const float* b5  = (const float*)d_in[13];
    const float* W6  = (const float*)d_in[14];
    const float* b6  = (const float*)d_in[15];
    float* out = (float*)d_out;

    const int smem_uv = (H_ * 52 + D_ * K_) * 4;
    cudaFuncSetAttribute(prep_uv,        cudaFuncAttributeMaxDynamicSharedMemorySize, smem_uv);
    cudaFuncSetAttribute(rn_pair_kernel, cudaFuncAttributeMaxDynamicSharedMemorySize, SMEM_PAIR);

    prep_uv<<<B_, 512, smem_uv>>>(x, W0, b0);
    prep_w<<<(3 * H_ * H_ + 255) / 256, 256>>>(W1, W2, W3);
    rn_pair_kernel<<<dim3(D_ / 2, B_), 512, SMEM_PAIR>>>(b1, b2, b3);
    rn_head_kernel<<<B_, 1024>>>(qst, W4, b4, W5, b5, W6, b6, out);
}

// round 14
// speedup vs baseline: 2.3693x; 1.0359x over previous
#include <cuda_runtime.h>
#include <cuda_fp16.h>
#include <cstdint>
#include <math.h>

typedef unsigned int U32;
typedef unsigned long long ULL;

#define B_    32
#define D_    64
#define K_    26
#define QST_  256
#define H_    512
#define NANS  28

// ---- pair-kernel SMEM map (bytes) ----
#define AOFF      0          // A: 128 rows x 512 fp16, row stride 1024B, XOR swizzle (128KB)
#define WOFF      131072     // 3-stage ring x 32KB weight chunks
#define BIASOFF   229376     // 512 floats
#define SMEM_PAIR 231424

// ---- device scratch ----
__device__ float  g_u[B_ * D_ * H_];
__device__ float  g_v[B_ * D_ * H_];
__device__ float  g_part[B_ * D_ * H_];
// weights, ldmatrix-ready: chunk g = (l*2+nch)*16+kc, 32KB each:
// [term(2)][ks(2)] blocks of 8KB = 256 n-rows x 32B, XOR-swizzled
__device__ __half g_Wh[3 * 2 * 16 * 2 * 2 * 4096];
// chunk-0 activation stash: [cta(1024)][tid(512)][8 x uint4]
__device__ uint4  g_stash[1024 * 512 * 8];

// =====================================================================
// helpers
// =====================================================================
__device__ __forceinline__ U32 smem_u32(const void* p) {
    U32 a;
    asm("{ .reg .u64 t; cvta.to.shared.u64 t, %1; cvt.u32.u64 %0, t; }" : "=r"(a) : "l"(p));
    return a;
}
__device__ __forceinline__ void cpasync16(U32 smem, const void* g) {
    asm volatile("cp.async.cg.shared.global [%0], [%1], 16;" :: "r"(smem), "l"(g));
}
#define CP_COMMIT() asm volatile("cp.async.commit_group;" ::: "memory")
#define CP_WAIT1()  asm volatile("cp.async.wait_group 1;" ::: "memory")
#define CP_WAIT0()  asm volatile("cp.async.wait_group 0;" ::: "memory")

__device__ __forceinline__ void ldm_x4(U32& r0, U32& r1, U32& r2, U32& r3, U32 addr) {
    asm volatile("ldmatrix.sync.aligned.m8n8.x4.shared.b16 {%0,%1,%2,%3}, [%4];"
                 : "=r"(r0), "=r"(r1), "=r"(r2), "=r"(r3) : "r"(addr));
}
__device__ __forceinline__ void mma16816(float& d0, float& d1, float& d2, float& d3,
                                         U32 a0, U32 a1, U32 a2, U32 a3, U32 b0, U32 b1) {
    asm volatile("mma.sync.aligned.m16n8k16.row.col.f32.f16.f16.f32 "
                 "{%0,%1,%2,%3}, {%4,%5,%6,%7}, {%8,%9}, {%0,%1,%2,%3};"
                 : "+f"(d0), "+f"(d1), "+f"(d2), "+f"(d3)
                 : "r"(a0), "r"(a1), "r"(a2), "r"(a3), "r"(b0), "r"(b1));
}
__device__ __forceinline__ U32 pack_h2(float a, float b) {
    return (U32)__half_as_ushort(__float2half_rn(a)) |
           ((U32)__half_as_ushort(__float2half_rn(b)) << 16);
}
// A-tile address: row stride 1024B, XOR bits[4:6] with (row&7)<<4
__device__ __forceinline__ U32 a_addr(U32 smem, int row, U32 colbyte) {
    return smem + AOFF + (U32)row * 1024u + (colbyte ^ (U32)((row & 7) << 4));
}
__device__ __forceinline__ void stsh32(U32 addr, U32 v) {
    asm volatile("st.shared.b32 [%0], %1;" :: "r"(addr), "r"(v) : "memory");
}

// =====================================================================
// Prep 1: per-object projections u, v (folds layer 0: 64x cheaper)
// =====================================================================
__global__ void prep_uv(const float* __restrict__ x,
                        const float* __restrict__ W0,
                        const float* __restrict__ b0) {
    extern __shared__ float smf[];
    float* Ws = smf;
    float* xs = smf + H_ * 52;
    int b = blockIdx.x, tid = threadIdx.x;
    for (int i = tid; i < H_ * 52; i += blockDim.x) Ws[i] = W0[i];
    for (int i = tid; i < D_ * K_; i += blockDim.x) xs[i] = x[b * D_ * K_ + i];
    __syncthreads();
    float bb = b0[tid];
    const float* w = Ws + tid * 52;
    for (int o = 0; o < D_; ++o) {
        const float* xo = xs + o * K_;
        float u = 0.f, v = 0.f;
#pragma unroll
        for (int j = 0; j < K_; ++j) {
            u = fmaf(w[j],      xo[j], u);
            v = fmaf(w[26 + j], xo[j], v);
        }
        g_u[(b * D_ + o) * H_ + tid] = u;
        g_v[(b * D_ + o) * H_ + tid] = v + bb;
    }
}

// =====================================================================
// Prep 2: split W1..W3 into fp16 hi/lo, ldmatrix-ready swizzled blocks.
// chunk g = (l*2+nch)*16+kc (32KB): [term(2)][ks(2)] 8KB blocks of
// 256 n-rows x 32B; byte = ((nr*32 + kpart*16) ^ (((nr>>2)&1)<<4)) + (kk&7)*2
// =====================================================================
__global__ void prep_w(const float* __restrict__ W1,
                       const float* __restrict__ W2,
                       const float* __restrict__ W3) {
    int idx = blockIdx.x * blockDim.x + threadIdx.x;
    if (idx >= 3 * H_ * H_) return;
    int l = idx / (H_ * H_);
    int rem = idx - l * H_ * H_;
    int n = rem >> 9, k = rem & 511;
    const float* W = (l == 0) ? W1 : ((l == 1) ? W2 : W3);
    float w = W[n * H_ + k];
    __half hi = __float2half_rn(w);
    __half lo = __float2half_rn(w - __half2float(hi));
    int nch = n >> 8, nr = n & 255;
    int kc = k >> 5, ks = (k >> 4) & 1, kk = k & 15;
    U32 inner = (U32)((nr * 32 + ((kk >> 3) << 4)) ^ (((nr >> 2) & 1) << 4)) + (U32)((kk & 7) * 2);
    char* base = (char*)g_Wh + (size_t)((l * 2 + nch) * 16 + kc) * 32768;
    *(__half*)(base + (size_t)(0 * 2 + ks) * 8192 + inner) = hi;
    *(__half*)(base + (size_t)(1 * 2 + ks) * 8192 + inner) = lo;
}

// =====================================================================
// Main pair kernel: HMMA fused layer0 + 3x(512x512) + aggregation.
// grid = (32, 32): p0 = 2*blockIdx.x, b = blockIdx.y. 512 threads.
// Warp grid 4(row) x 4(col): warp tile m32 x n64 (acc = 64 regs) ->
// LDSM per chunk drops 34 -> 20 (SMEM crossbar no longer binding).
// 96-chunk stream, 3-stage ring, one barrier per chunk, 2-chunk lookahead.
// =====================================================================
__global__ __launch_bounds__(512, 1)
void rn_pair_kernel(const float* __restrict__ b1,
                    const float* __restrict__ b2,
                    const float* __restrict__ b3) {
    extern __shared__ __align__(16) char smc[];
    const U32 smem = smem_u32(smc);
    float* bsm = (float*)(smc + BIASOFF);
    const int tid = threadIdx.x;
    const int wid = tid >> 5, lane = tid & 31;
    const int rg = wid & 3, cg = wid >> 2;          // 4 row groups x 4 col groups
    const int b = blockIdx.y;
    const int p0 = blockIdx.x * 2;
    const int cta = b * 32 + blockIdx.x;

    // chunk-stream loader: chunk g -> ring buffer g%3
    auto load_stage = [&](int g) {
        const char* src = (const char*)g_Wh + (size_t)g * 32768 + tid * 16;
        U32 d = smem + WOFF + (U32)(g % 3) * 32768 + (U32)tid * 16;
#pragma unroll
        for (int j = 0; j < 4; ++j)
            cpasync16(d + (U32)j * 8192, src + (size_t)j * 8192);
        CP_COMMIT();
    };

    // prologue: start streaming before the layer-0 fill to bury L2 latency
    load_stage(0);
    load_stage(1);

    // ---- layer 0 fill: A[r][c] = fp16(relu(u[b, r&63, c] + v[b, p0+(r>>6), c])) ----
    {
        const int r = tid >> 2, qd = tid & 3;
        const int q = r & 63, p = p0 + (r >> 6);
        const float4* u4 = (const float4*)(g_u + (size_t)(b * D_ + q) * H_);
        const float4* v4 = (const float4*)(g_v + (size_t)(b * D_ + p) * H_);
#pragma unroll 4
        for (int it = 0; it < 16; ++it) {
            int c4 = qd * 32 + it * 2;
            float4 ua = u4[c4], ub = u4[c4 + 1], va = v4[c4], vb = v4[c4 + 1];
            float t0 = fmaxf(ua.x + va.x, 0.f), t1 = fmaxf(ua.y + va.y, 0.f);
            float t2 = fmaxf(ua.z + va.z, 0.f), t3 = fmaxf(ua.w + va.w, 0.f);
            float t4 = fmaxf(ub.x + vb.x, 0.f), t5 = fmaxf(ub.y + vb.y, 0.f);
            float t6 = fmaxf(ub.z + vb.z, 0.f), t7 = fmaxf(ub.w + vb.w, 0.f);
            U32 p0w = pack_h2(t0, t1), p1w = pack_h2(t2, t3);
            U32 p2w = pack_h2(t4, t5), p3w = pack_h2(t6, t7);
            U32 addr = a_addr(smem, r, (U32)(qd * 256 + it * 16));
            asm volatile("st.shared.v4.b32 [%0], {%1,%2,%3,%4};"
                         :: "r"(addr), "r"(p0w), "r"(p1w), "r"(p2w), "r"(p3w) : "memory");
        }
    }

    // per-thread invariant ldmatrix address parts
    const int arow = rg * 32 + (lane & 15);                 // A frag row (first m16)
    const U32 arsw = (U32)((arow & 7) << 4);                // same for row+16
    const U32 arbase0 = smem + AOFF + (U32)arow * 1024u;
    const U32 arbase1 = arbase0 + 16 * 1024u;               // second m16
    const U32 al16 = (U32)(lane & 16);                      // +16B for k+8 halves
    const int bd = (lane & 7) + ((lane & 16) >> 1);         // B n-row within 16-row group
    const U32 bT = (U32)(cg * 2048) +                       // col-group: 64-row slice of 256
                   (U32)((bd * 32 + (((lane >> 3) & 1) << 4)) ^ (((bd >> 2) & 1) << 4));

    int g = 0;
    for (int l = 0; l < 3; ++l) {
        const float* bias = (l == 0) ? b1 : ((l == 1) ? b2 : b3);
        bsm[tid] = bias[tid];   // ordered before epilogue reads by in-loop barriers

        for (int nch = 0; nch < 2; ++nch) {
            float acc[16][4];
#pragma unroll
            for (int f = 0; f < 16; ++f) {
                acc[f][0] = 0.f; acc[f][1] = 0.f; acc[f][2] = 0.f; acc[f][3] = 0.f;
            }

            for (int kc = 0; kc < 16; ++kc, ++g) {
                if (g < 95) CP_WAIT1(); else CP_WAIT0();  // chunk g's copies done (mine)
                __syncthreads();                           // all copies visible; compute(g-1) done
                if (g + 2 < 96) load_stage(g + 2);         // buf (g-1)%3, freed by barrier

                const U32 wb = smem + WOFF + (U32)(g % 3) * 32768;
#pragma unroll
                for (int ks = 0; ks < 2; ++ks) {
                    // A fragments: two m16 tiles, shared between hi and lo terms
                    U32 cb = (U32)(kc * 64 + ks * 32) + al16;
                    U32 a0, a1, a2, a3, a4, a5, a6, a7;
                    ldm_x4(a0, a1, a2, a3, arbase0 + (cb ^ arsw));
                    ldm_x4(a4, a5, a6, a7, arbase1 + (cb ^ arsw));
#pragma unroll
                    for (int t = 0; t < 2; ++t) {
                        const U32 bb = wb + (U32)((t * 2 + ks) * 8192) + bT;
#pragma unroll
                        for (int fp = 0; fp < 4; ++fp) {   // 4 n16 groups = n64
                            U32 b0, b1, b2c, b3c;
                            ldm_x4(b0, b1, b2c, b3c, bb + (U32)(fp * 512));
                            mma16816(acc[2*fp][0], acc[2*fp][1], acc[2*fp][2], acc[2*fp][3],
                                     a0, a1, a2, a3, b0, b1);
                            mma16816(acc[2*fp+1][0], acc[2*fp+1][1], acc[2*fp+1][2], acc[2*fp+1][3],
                                     a0, a1, a2, a3, b2c, b3c);
                            mma16816(acc[8+2*fp][0], acc[8+2*fp][1], acc[8+2*fp][2], acc[8+2*fp][3],
                                     a4, a5, a6, a7, b0, b1);
                            mma16816(acc[8+2*fp+1][0], acc[8+2*fp+1][1], acc[8+2*fp+1][2], acc[8+2*fp+1][3],
                                     a4, a5, a6, a7, b2c, b3c);
                        }
                    }
                }
            }

            // ---- epilogue: +bias, relu, pack fp16 pairs ----
            // frag f = mi*8 + fp2 (mi = m16 half, fp2 = n8 group within n64)
            U32 pk[32];
#pragma unroll
            for (int f = 0; f < 16; ++f) {
                int fp2 = f & 7;
                int nc = nch * 256 + cg * 64 + fp2 * 8 + ((lane & 3) << 1);
                float bx = bsm[nc], by = bsm[nc + 1];
                pk[2 * f]     = pack_h2(fmaxf(acc[f][0] + bx, 0.f), fmaxf(acc[f][1] + by, 0.f));
                pk[2 * f + 1] = pack_h2(fmaxf(acc[f][2] + bx, 0.f), fmaxf(acc[f][3] + by, 0.f));
            }

            if (nch == 0) {
                // stash chunk-0 output per-thread-contiguous in global scratch
                uint4* dst = g_stash + ((size_t)cta * 512 + tid) * 8;
#pragma unroll
                for (int j = 0; j < 8; ++j)
                    dst[j] = make_uint4(pk[4*j], pk[4*j+1], pk[4*j+2], pk[4*j+3]);
                // A still read next pass: no A writes here
            } else {
                __syncthreads();   // last chunk's A reads done before overwrite
                const int rbase = rg * 32 + (lane >> 2);
                // chunk-1 -> A[:,256:512]
#pragma unroll
                for (int f = 0; f < 16; ++f) {
                    int mi = f >> 3, fp2 = f & 7;
                    int nc = 256 + cg * 64 + fp2 * 8 + ((lane & 3) << 1);
                    int row = rbase + mi * 16;
                    stsh32(a_addr(smem, row,     (U32)(nc * 2)), pk[2*f]);
                    stsh32(a_addr(smem, row + 8, (U32)(nc * 2)), pk[2*f+1]);
                }
                // chunk-0 stash -> A[:,0:256]  (own data; no fence needed)
                const uint4* src = g_stash + ((size_t)cta * 512 + tid) * 8;
#pragma unroll
                for (int j = 0; j < 8; ++j) {
                    uint4 s = src[j];
                    U32 q0[4] = { s.x, s.y, s.z, s.w };
#pragma unroll
                    for (int c = 0; c < 4; ++c) {
                        int i = j * 4 + c, f = i >> 1, h = i & 1;
                        int mi = f >> 3, fp2 = f & 7;
                        int nc = cg * 64 + fp2 * 8 + ((lane & 3) << 1);
                        int row = rbase + mi * 16 + h * 8;
                        stsh32(a_addr(smem, row, (U32)(nc * 2)), q0[c]);
                    }
                }
                __syncthreads();   // A complete (and bias free) before next layer
            }
        }
    }

    // ---- deterministic aggregation: per (p-half, col-pair) sums over 64 rows ----
    {
        const int gg = tid >> 8, c2 = (tid & 255) * 2;
        float s0 = 0.f, s1 = 0.f;
#pragma unroll 8
        for (int rr = 0; rr < 64; ++rr) {
            int r = gg * 64 + rr;
            U32 h2;
            asm volatile("ld.shared.b32 %0, [%1];" : "=r"(h2)
                         : "r"(a_addr(smem, r, (U32)(c2 * 2))));
            s0 += __half2float(__ushort_as_half((unsigned short)(h2 & 0xffff)));
            s1 += __half2float(__ushort_as_half((unsigned short)(h2 >> 16)));
        }
        g_part[((size_t)b * D_ + p0 + gg) * H_ + c2]     = s0;
        g_part[((size_t)b * D_ + p0 + gg) * H_ + c2 + 1] = s1;
    }
}

// =====================================================================
// Head: reduce partials, concat qst, layers 4-6, log_softmax.
// grid = 32, block = 1024 (32 warps, float4 warp-dots).
// =====================================================================
__global__ __launch_bounds__(1024)
void rn_head_kernel(const float* __restrict__ qst,
                    const float* __restrict__ W4, const float* __restrict__ b4,
                    const float* __restrict__ W5, const float* __restrict__ b5,
                    const float* __restrict__ W6, const float* __restrict__ b6,
                    float* __restrict__ out) {
    __shared__ float red[1024];
    __shared__ __align__(16) float hin[H_ + QST_];
    __shared__ __align__(16) float h4[H_];
    __shared__ __align__(16) float h5[H_];
    __shared__ float logits[NANS];
    const int b = blockIdx.x, tid = threadIdx.x;
    const int w = tid >> 5, lane = tid & 31;

    {
        const int c = tid & 511, hh = tid >> 9;
        const float* pp = g_part + ((size_t)b * D_ + hh * 32) * H_ + c;
        float s = 0.f;
#pragma unroll 8
        for (int r = 0; r < 32; ++r) s += pp[r * H_];
        red[tid] = s;
    }
    __syncthreads();
    if (tid < H_) hin[tid] = red[tid] + red[tid + 512];
    else if (tid < H_ + QST_) hin[tid] = qst[b * QST_ + (tid - H_)];
    __syncthreads();

    for (int k = 0; k < 16; ++k) {                        // layer 4: 768 -> 512
        const int o = w * 16 + k;
        const float4* wr = (const float4*)(W4 + (size_t)o * (H_ + QST_));
        const float4* hv = (const float4*)hin;
        float a = 0.f;
#pragma unroll
        for (int m = 0; m < 6; ++m) {
            float4 x4 = wr[lane + 32 * m], y4 = hv[lane + 32 * m];
            a += x4.x * y4.x + x4.y * y4.y + x4.z * y4.z + x4.w * y4.w;
        }
#pragma unroll
        for (int off = 16; off; off >>= 1) a += __shfl_xor_sync(0xffffffffu, a, off);
        if (lane == 0) { float t = a + b4[o]; h4[o] = t > 0.f ? t : 0.f; }
    }
    __syncthreads();

    for (int k = 0; k < 16; ++k) {                        // layer 5: 512 -> 512
        const int o = w * 16 + k;
        const float4* wr = (const float4*)(W5 + (size_t)o * H_);
        const float4* hv = (const float4*)h4;
        float a = 0.f;
#pragma unroll
        for (int m = 0; m < 4; ++m) {
            float4 x4 = wr[lane + 32 * m], y4 = hv[lane + 32 * m];
            a += x4.x * y4.x + x4.y * y4.y + x4.z * y4.z + x4.w * y4.w;
        }
#pragma unroll
        for (int off = 16; off; off >>= 1) a += __shfl_xor_sync(0xffffffffu, a, off);
        if (lane == 0) { float t = a + b5[o]; h5[o] = t > 0.f ? t : 0.f; }
    }
    __syncthreads();

    if (w < NANS) {                                       // layer 6: 512 -> 28
        const float4* wr = (const float4*)(W6 + (size_t)w * H_);
        const float4* hv = (const float4*)h5;
        float a = 0.f;
#pragma unroll
        for (int m = 0; m < 4; ++m) {
            float4 x4 = wr[lane + 32 * m], y4 = hv[lane + 32 * m];
            a += x4.x * y4.x + x4.y * y4.y + x4.z * y4.z + x4.w * y4.w;
        }
#pragma unroll
        for (int off = 16; off; off >>= 1) a += __shfl_xor_sync(0xffffffffu, a, off);
        if (lane == 0) logits[w] = a + b6[w];
    }
    __syncthreads();

    if (w == 0) {
        float z = lane < NANS ? logits[lane] : -INFINITY;
        float m = z;
#pragma unroll
        for (int off = 16; off; off >>= 1) m = fmaxf(m, __shfl_xor_sync(0xffffffffu, m, off));
        float e = lane < NANS ? expf(z - m) : 0.f;
        float s = e;
#pragma unroll
        for (int off = 16; off; off >>= 1) s += __shfl_xor_sync(0xffffffffu, s, off);
        if (lane < NANS) out[b * NANS + lane] = z - m - logf(s);
    }
}

// =====================================================================
extern "C" void kernel_launch(void* const* d_in, const int* in_sizes, int n_in,
                              void* d_out, int out_size) {
    const float* x   = (const float*)d_in[0];
    const float* qst = (const float*)d_in[1];
    const float* W0  = (const float*)d_in[2];
    const float* b0  = (const float*)d_in[3];
    const float* W1  = (const float*)d_in[4];
    const float* b1  = (const float*)d_in[5];
    const float* W2  = (const float*)d_in[6];
    const float* b2  = (const float*)d_in[7];
    const float* W3  = (const float*)d_in[8];
    const float* b3  = (const float*)d_in[9];
    const float* W4  = (const float*)d_in[10];
    const float* b4  = (const float*)d_in[11];
    const float* W5  = (const float*)d_in[12];
    const float* b5  = (const float*)d_in[13];
    const float* W6  = (const float*)d_in[14];
    const float* b6  = (const float*)d_in[15];
    float* out = (float*)d_out;

    const int smem_uv = (H_ * 52 + D_ * K_) * 4;
    cudaFuncSetAttribute(prep_uv,        cudaFuncAttributeMaxDynamicSharedMemorySize, smem_uv);
    cudaFuncSetAttribute(rn_pair_kernel, cudaFuncAttributeMaxDynamicSharedMemorySize, SMEM_PAIR);

    prep_uv<<<B_, 512, smem_uv>>>(x, W0, b0);
    prep_w<<<(3 * H_ * H_ + 255) / 256, 256>>>(W1, W2, W3);
    rn_pair_kernel<<<dim3(D_ / 2, B_), 512, SMEM_PAIR>>>(b1, b2, b3);
    rn_head_kernel<<<B_, 1024>>>(qst, W4, b4, W5, b5, W6, b6, out);
}

// round 15
// speedup vs baseline: 2.4105x; 1.0174x over previous
#include <cuda_runtime.h>
#include <cuda_fp16.h>
#include <cstdint>
#include <math.h>

typedef unsigned int U32;
typedef unsigned long long ULL;

#define B_    32
#define D_    64
#define K_    26
#define QST_  256
#define H_    512
#define NANS  28

// ---- pair-kernel SMEM map (bytes) ----
#define AOFF      0          // A: 128 rows x 512 fp16, row stride 1024B, XOR swizzle (128KB)
#define WOFF      131072     // 3-stage ring x 32KB weight chunks
#define BIASOFF   229376     // 512 floats
#define SMEM_PAIR 231424

// ---- device scratch ----
__device__ float  g_u[B_ * D_ * H_];
__device__ float  g_v[B_ * D_ * H_];
__device__ float  g_part[B_ * D_ * H_];
// weights (fp16, hi only), ldmatrix-ready: chunk g = (l*2+nch)*8+kq, 32KB each:
// [ks16(4)] blocks of 8KB = 256 n-rows x 32B, XOR-swizzled. 48 chunks total.
__device__ __half g_Wh[3 * 2 * 8 * 4 * 4096];
// chunk-0 activation stash: [cta(1024)][tid(512)][8 x uint4]
__device__ uint4  g_stash[1024 * 512 * 8];

// =====================================================================
// helpers
// =====================================================================
__device__ __forceinline__ U32 smem_u32(const void* p) {
    U32 a;
    asm("{ .reg .u64 t; cvta.to.shared.u64 t, %1; cvt.u32.u64 %0, t; }" : "=r"(a) : "l"(p));
    return a;
}
__device__ __forceinline__ void cpasync16(U32 smem, const void* g) {
    asm volatile("cp.async.cg.shared.global [%0], [%1], 16;" :: "r"(smem), "l"(g));
}
#define CP_COMMIT() asm volatile("cp.async.commit_group;" ::: "memory")
#define CP_WAIT1()  asm volatile("cp.async.wait_group 1;" ::: "memory")
#define CP_WAIT0()  asm volatile("cp.async.wait_group 0;" ::: "memory")

__device__ __forceinline__ void ldm_x4(U32& r0, U32& r1, U32& r2, U32& r3, U32 addr) {
    asm volatile("ldmatrix.sync.aligned.m8n8.x4.shared.b16 {%0,%1,%2,%3}, [%4];"
                 : "=r"(r0), "=r"(r1), "=r"(r2), "=r"(r3) : "r"(addr));
}
__device__ __forceinline__ void mma16816(float& d0, float& d1, float& d2, float& d3,
                                         U32 a0, U32 a1, U32 a2, U32 a3, U32 b0, U32 b1) {
    asm volatile("mma.sync.aligned.m16n8k16.row.col.f32.f16.f16.f32 "
                 "{%0,%1,%2,%3}, {%4,%5,%6,%7}, {%8,%9}, {%0,%1,%2,%3};"
                 : "+f"(d0), "+f"(d1), "+f"(d2), "+f"(d3)
                 : "r"(a0), "r"(a1), "r"(a2), "r"(a3), "r"(b0), "r"(b1));
}
__device__ __forceinline__ U32 pack_h2(float a, float b) {
    return (U32)__half_as_ushort(__float2half_rn(a)) |
           ((U32)__half_as_ushort(__float2half_rn(b)) << 16);
}
// A-tile address: row stride 1024B, XOR bits[4:6] with (row&7)<<4
__device__ __forceinline__ U32 a_addr(U32 smem, int row, U32 colbyte) {
    return smem + AOFF + (U32)row * 1024u + (colbyte ^ (U32)((row & 7) << 4));
}
__device__ __forceinline__ void stsh32(U32 addr, U32 v) {
    asm volatile("st.shared.b32 [%0], %1;" :: "r"(addr), "r"(v) : "memory");
}

// =====================================================================
// Prep 1: per-object projections u, v (folds layer 0: 64x cheaper)
// =====================================================================
__global__ void prep_uv(const float* __restrict__ x,
                        const float* __restrict__ W0,
                        const float* __restrict__ b0) {
    extern __shared__ float smf[];
    float* Ws = smf;
    float* xs = smf + H_ * 52;
    int b = blockIdx.x, tid = threadIdx.x;
    for (int i = tid; i < H_ * 52; i += blockDim.x) Ws[i] = W0[i];
    for (int i = tid; i < D_ * K_; i += blockDim.x) xs[i] = x[b * D_ * K_ + i];
    __syncthreads();
    float bb = b0[tid];
    const float* w = Ws + tid * 52;
    for (int o = 0; o < D_; ++o) {
        const float* xo = xs + o * K_;
        float u = 0.f, v = 0.f;
#pragma unroll
        for (int j = 0; j < K_; ++j) {
            u = fmaf(w[j],      xo[j], u);
            v = fmaf(w[26 + j], xo[j], v);
        }
        g_u[(b * D_ + o) * H_ + tid] = u;
        g_v[(b * D_ + o) * H_ + tid] = v + bb;
    }
}

// =====================================================================
// Prep 2: W1..W3 -> fp16 (hi only), ldmatrix-ready swizzled blocks.
// chunk g = (l*2+nch)*8+kq (32KB, k64): [ks16(4)] 8KB blocks of
// 256 n-rows x 32B; byte = ((nr*32 + kpart*16) ^ (((nr>>2)&1)<<4)) + (kk&7)*2
// =====================================================================
__global__ void prep_w(const float* __restrict__ W1,
                       const float* __restrict__ W2,
                       const float* __restrict__ W3) {
    int idx = blockIdx.x * blockDim.x + threadIdx.x;
    if (idx >= 3 * H_ * H_) return;
    int l = idx / (H_ * H_);
    int rem = idx - l * H_ * H_;
    int n = rem >> 9, k = rem & 511;
    const float* W = (l == 0) ? W1 : ((l == 1) ? W2 : W3);
    __half hi = __float2half_rn(W[n * H_ + k]);
    int nch = n >> 8, nr = n & 255;
    int kq = k >> 6, ks16 = (k >> 4) & 3, kk = k & 15;
    U32 inner = (U32)((nr * 32 + ((kk >> 3) << 4)) ^ (((nr >> 2) & 1) << 4)) + (U32)((kk & 7) * 2);
    char* base = (char*)g_Wh + (size_t)((l * 2 + nch) * 8 + kq) * 32768;
    *(__half*)(base + (size_t)ks16 * 8192 + inner) = hi;
}

// =====================================================================
// Main pair kernel: HMMA fused layer0 + 3x(512x512) + aggregation.
// grid = (32, 32): p0 = 2*blockIdx.x, b = blockIdx.y. 512 threads.
// Warp grid 4(row) x 4(col): warp tile m32 x n64 (acc = 64 regs).
// 48-chunk stream (k64 per chunk, hi-only weights), 3-stage ring,
// one barrier per chunk, 2-chunk lookahead.
// =====================================================================
__global__ __launch_bounds__(512, 1)
void rn_pair_kernel(const float* __restrict__ b1,
                    const float* __restrict__ b2,
                    const float* __restrict__ b3) {
    extern __shared__ __align__(16) char smc[];
    const U32 smem = smem_u32(smc);
    float* bsm = (float*)(smc + BIASOFF);
    const int tid = threadIdx.x;
    const int wid = tid >> 5, lane = tid & 31;
    const int rg = wid & 3, cg = wid >> 2;          // 4 row groups x 4 col groups
    const int b = blockIdx.y;
    const int p0 = blockIdx.x * 2;
    const int cta = b * 32 + blockIdx.x;

    // chunk-stream loader: chunk g -> ring buffer g%3
    auto load_stage = [&](int g) {
        const char* src = (const char*)g_Wh + (size_t)g * 32768 + tid * 16;
        U32 d = smem + WOFF + (U32)(g % 3) * 32768 + (U32)tid * 16;
#pragma unroll
        for (int j = 0; j < 4; ++j)
            cpasync16(d + (U32)j * 8192, src + (size_t)j * 8192);
        CP_COMMIT();
    };

    // prologue: start streaming before the layer-0 fill to bury L2 latency
    load_stage(0);
    load_stage(1);

    // ---- layer 0 fill: A[r][c] = fp16(relu(u[b, r&63, c] + v[b, p0+(r>>6), c])) ----
    {
        const int r = tid >> 2, qd = tid & 3;
        const int q = r & 63, p = p0 + (r >> 6);
        const float4* u4 = (const float4*)(g_u + (size_t)(b * D_ + q) * H_);
        const float4* v4 = (const float4*)(g_v + (size_t)(b * D_ + p) * H_);
#pragma unroll 4
        for (int it = 0; it < 16; ++it) {
            int c4 = qd * 32 + it * 2;
            float4 ua = u4[c4], ub = u4[c4 + 1], va = v4[c4], vb = v4[c4 + 1];
            float t0 = fmaxf(ua.x + va.x, 0.f), t1 = fmaxf(ua.y + va.y, 0.f);
            float t2 = fmaxf(ua.z + va.z, 0.f), t3 = fmaxf(ua.w + va.w, 0.f);
            float t4 = fmaxf(ub.x + vb.x, 0.f), t5 = fmaxf(ub.y + vb.y, 0.f);
            float t6 = fmaxf(ub.z + vb.z, 0.f), t7 = fmaxf(ub.w + vb.w, 0.f);
            U32 p0w = pack_h2(t0, t1), p1w = pack_h2(t2, t3);
            U32 p2w = pack_h2(t4, t5), p3w = pack_h2(t6, t7);
            U32 addr = a_addr(smem, r, (U32)(qd * 256 + it * 16));
            asm volatile("st.shared.v4.b32 [%0], {%1,%2,%3,%4};"
                         :: "r"(addr), "r"(p0w), "r"(p1w), "r"(p2w), "r"(p3w) : "memory");
        }
    }

    // per-thread invariant ldmatrix address parts
    const int arow = rg * 32 + (lane & 15);                 // A frag row (first m16)
    const U32 arsw = (U32)((arow & 7) << 4);                // same for row+16
    const U32 arbase0 = smem + AOFF + (U32)arow * 1024u;
    const U32 arbase1 = arbase0 + 16 * 1024u;               // second m16
    const U32 al16 = (U32)(lane & 16);                      // +16B for k+8 halves
    const int bd = (lane & 7) + ((lane & 16) >> 1);         // B n-row within 16-row group
    const U32 bT = (U32)(cg * 2048) +                       // col-group: 64-row slice of 256
                   (U32)((bd * 32 + (((lane >> 3) & 1) << 4)) ^ (((bd >> 2) & 1) << 4));

    int g = 0;
    for (int l = 0; l < 3; ++l) {
        const float* bias = (l == 0) ? b1 : ((l == 1) ? b2 : b3);
        bsm[tid] = bias[tid];   // ordered before epilogue reads by in-loop barriers

        for (int nch = 0; nch < 2; ++nch) {
            float acc[16][4];
#pragma unroll
            for (int f = 0; f < 16; ++f) {
                acc[f][0] = 0.f; acc[f][1] = 0.f; acc[f][2] = 0.f; acc[f][3] = 0.f;
            }

            for (int kc = 0; kc < 8; ++kc, ++g) {        // 8 chunks of k64 per pass
                if (g < 47) CP_WAIT1(); else CP_WAIT0(); // chunk g's copies done (mine)
                __syncthreads();                          // all copies visible; compute(g-1) done
                if (g + 2 < 48) load_stage(g + 2);        // buf (g-1)%3, freed by barrier

                const U32 wb = smem + WOFF + (U32)(g % 3) * 32768;
#pragma unroll
                for (int ks = 0; ks < 4; ++ks) {          // 4 k16 steps within k64
                    // A fragments: two m16 tiles
                    U32 cb = (U32)(kc * 128 + ks * 32) + al16;
                    U32 a0, a1, a2, a3, a4, a5, a6, a7;
                    ldm_x4(a0, a1, a2, a3, arbase0 + (cb ^ arsw));
                    ldm_x4(a4, a5, a6, a7, arbase1 + (cb ^ arsw));
                    const U32 bb = wb + (U32)(ks * 8192) + bT;
#pragma unroll
                    for (int fp = 0; fp < 4; ++fp) {      // 4 n16 groups = n64
                        U32 b0, b1, b2c, b3c;
                        ldm_x4(b0, b1, b2c, b3c, bb + (U32)(fp * 512));
                        mma16816(acc[2*fp][0], acc[2*fp][1], acc[2*fp][2], acc[2*fp][3],
                                 a0, a1, a2, a3, b0, b1);
                        mma16816(acc[2*fp+1][0], acc[2*fp+1][1], acc[2*fp+1][2], acc[2*fp+1][3],
                                 a0, a1, a2, a3, b2c, b3c);
                        mma16816(acc[8+2*fp][0], acc[8+2*fp][1], acc[8+2*fp][2], acc[8+2*fp][3],
                                 a4, a5, a6, a7, b0, b1);
                        mma16816(acc[8+2*fp+1][0], acc[8+2*fp+1][1], acc[8+2*fp+1][2], acc[8+2*fp+1][3],
                                 a4, a5, a6, a7, b2c, b3c);
                    }
                }
            }

            // ---- epilogue: +bias, relu, pack fp16 pairs ----
            // frag f = mi*8 + fp2 (mi = m16 half, fp2 = n8 group within n64)
            U32 pk[32];
#pragma unroll
            for (int f = 0; f < 16; ++f) {
                int fp2 = f & 7;
                int nc = nch * 256 + cg * 64 + fp2 * 8 + ((lane & 3) << 1);
                float bx = bsm[nc], by = bsm[nc + 1];
                pk[2 * f]     = pack_h2(fmaxf(acc[f][0] + bx, 0.f), fmaxf(acc[f][1] + by, 0.f));
                pk[2 * f + 1] = pack_h2(fmaxf(acc[f][2] + bx, 0.f), fmaxf(acc[f][3] + by, 0.f));
            }

            if (nch == 0) {
                // stash chunk-0 output per-thread-contiguous in global scratch
                uint4* dst = g_stash + ((size_t)cta * 512 + tid) * 8;
#pragma unroll
                for (int j = 0; j < 8; ++j)
                    dst[j] = make_uint4(pk[4*j], pk[4*j+1], pk[4*j+2], pk[4*j+3]);
                // A still read next pass: no A writes here
            } else {
                __syncthreads();   // last chunk's A reads done before overwrite
                const int rbase = rg * 32 + (lane >> 2);
                // chunk-1 -> A[:,256:512]
#pragma unroll
                for (int f = 0; f < 16; ++f) {
                    int mi = f >> 3, fp2 = f & 7;
                    int nc = 256 + cg * 64 + fp2 * 8 + ((lane & 3) << 1);
                    int row = rbase + mi * 16;
                    stsh32(a_addr(smem, row,     (U32)(nc * 2)), pk[2*f]);
                    stsh32(a_addr(smem, row + 8, (U32)(nc * 2)), pk[2*f+1]);
                }
                // chunk-0 stash -> A[:,0:256]  (own data; no fence needed)
                const uint4* src = g_stash + ((size_t)cta * 512 + tid) * 8;
#pragma unroll
                for (int j = 0; j < 8; ++j) {
                    uint4 s = src[j];
                    U32 q0[4] = { s.x, s.y, s.z, s.w };
#pragma unroll
                    for (int c = 0; c < 4; ++c) {
                        int i = j * 4 + c, f = i >> 1, h = i & 1;
                        int mi = f >> 3, fp2 = f & 7;
                        int nc = cg * 64 + fp2 * 8 + ((lane & 3) << 1);
                        int row = rbase + mi * 16 + h * 8;
                        stsh32(a_addr(smem, row, (U32)(nc * 2)), q0[c]);
                    }
                }
                __syncthreads();   // A complete (and bias free) before next layer
            }
        }
    }

    // ---- deterministic aggregation: per (p-half, col-pair) sums over 64 rows ----
    {
        const int gg = tid >> 8, c2 = (tid & 255) * 2;
        float s0 = 0.f, s1 = 0.f;
#pragma unroll 8
        for (int rr = 0; rr < 64; ++rr) {
            int r = gg * 64 + rr;
            U32 h2;
            asm volatile("ld.shared.b32 %0, [%1];" : "=r"(h2)
                         : "r"(a_addr(smem, r, (U32)(c2 * 2))));
            s0 += __half2float(__ushort_as_half((unsigned short)(h2 & 0xffff)));
            s1 += __half2float(__ushort_as_half((unsigned short)(h2 >> 16)));
        }
        g_part[((size_t)b * D_ + p0 + gg) * H_ + c2]     = s0;
        g_part[((size_t)b * D_ + p0 + gg) * H_ + c2 + 1] = s1;
    }
}

// =====================================================================
// Head: reduce partials, concat qst, layers 4-6, log_softmax.
// grid = 32, block = 1024 (32 warps, float4 warp-dots).
// =====================================================================
__global__ __launch_bounds__(1024)
void rn_head_kernel(const float* __restrict__ qst,
                    const float* __restrict__ W4, const float* __restrict__ b4,
                    const float* __restrict__ W5, const float* __restrict__ b5,
                    const float* __restrict__ W6, const float* __restrict__ b6,
                    float* __restrict__ out) {
    __shared__ float red[1024];
    __shared__ __align__(16) float hin[H_ + QST_];
    __shared__ __align__(16) float h4[H_];
    __shared__ __align__(16) float h5[H_];
    __shared__ float logits[NANS];
    const int b = blockIdx.x, tid = threadIdx.x;
    const int w = tid >> 5, lane = tid & 31;

    {
        const int c = tid & 511, hh = tid >> 9;
        const float* pp = g_part + ((size_t)b * D_ + hh * 32) * H_ + c;
        float s = 0.f;
#pragma unroll 8
        for (int r = 0; r < 32; ++r) s += pp[r * H_];
        red[tid] = s;
    }
    __syncthreads();
    if (tid < H_) hin[tid] = red[tid] + red[tid + 512];
    else if (tid < H_ + QST_) hin[tid] = qst[b * QST_ + (tid - H_)];
    __syncthreads();

    for (int k = 0; k < 16; ++k) {                        // layer 4: 768 -> 512
        const int o = w * 16 + k;
        const float4* wr = (const float4*)(W4 + (size_t)o * (H_ + QST_));
        const float4* hv = (const float4*)hin;
        float a = 0.f;
#pragma unroll
        for (int m = 0; m < 6; ++m) {
            float4 x4 = wr[lane + 32 * m], y4 = hv[lane + 32 * m];
            a += x4.x * y4.x + x4.y * y4.y + x4.z * y4.z + x4.w * y4.w;
        }
#pragma unroll
        for (int off = 16; off; off >>= 1) a += __shfl_xor_sync(0xffffffffu, a, off);
        if (lane == 0) { float t = a + b4[o]; h4[o] = t > 0.f ? t : 0.f; }
    }
    __syncthreads();

    for (int k = 0; k < 16; ++k) {                        // layer 5: 512 -> 512
        const int o = w * 16 + k;
        const float4* wr = (const float4*)(W5 + (size_t)o * H_);
        const float4* hv = (const float4*)h4;
        float a = 0.f;
#pragma unroll
        for (int m = 0; m < 4; ++m) {
            float4 x4 = wr[lane + 32 * m], y4 = hv[lane + 32 * m];
            a += x4.x * y4.x + x4.y * y4.y + x4.z * y4.z + x4.w * y4.w;
        }
#pragma unroll
        for (int off = 16; off; off >>= 1) a += __shfl_xor_sync(0xffffffffu, a, off);
        if (lane == 0) { float t = a + b5[o]; h5[o] = t > 0.f ? t : 0.f; }
    }
    __syncthreads();

    if (w < NANS) {                                       // layer 6: 512 -> 28
        const float4* wr = (const float4*)(W6 + (size_t)w * H_);
        const float4* hv = (const float4*)h5;
        float a = 0.f;
#pragma unroll
        for (int m = 0; m < 4; ++m) {
            float4 x4 = wr[lane + 32 * m], y4 = hv[lane + 32 * m];
            a += x4.x * y4.x + x4.y * y4.y + x4.z * y4.z + x4.w * y4.w;
        }
#pragma unroll
        for (int off = 16; off; off >>= 1) a += __shfl_xor_sync(0xffffffffu, a, off);
        if (lane == 0) logits[w] = a + b6[w];
    }
    __syncthreads();

    if (w == 0) {
        float z = lane < NANS ? logits[lane] : -INFINITY;
        float m = z;
#pragma unroll
        for (int off = 16; off; off >>= 1) m = fmaxf(m, __shfl_xor_sync(0xffffffffu, m, off));
        float e = lane < NANS ? expf(z - m) : 0.f;
        float s = e;
#pragma unroll
        for (int off = 16; off; off >>= 1) s += __shfl_xor_sync(0xffffffffu, s, off);
        if (lane < NANS) out[b * NANS + lane] = z - m - logf(s);
    }
}

// =====================================================================
extern "C" void kernel_launch(void* const* d_in, const int* in_sizes, int n_in,
                              void* d_out, int out_size) {
    const float* x   = (const float*)d_in[0];
    const float* qst = (const float*)d_in[1];
    const float* W0  = (const float*)d_in[2];
    const float* b0  = (const float*)d_in[3];
    const float* W1  = (const float*)d_in[4];
    const float* b1  = (const float*)d_in[5];
    const float* W2  = (const float*)d_in[6];
    const float* b2  = (const float*)d_in[7];
    const float* W3  = (const float*)d_in[8];
    const float* b3  = (const float*)d_in[9];
    const float* W4  = (const float*)d_in[10];
    const float* b4  = (const float*)d_in[11];
    const float* W5  = (const float*)d_in[12];
    const float* b5  = (const float*)d_in[13];
    const float* W6  = (const float*)d_in[14];
    const float* b6  = (const float*)d_in[15];
    float* out = (float*)d_out;

    const int smem_uv = (H_ * 52 + D_ * K_) * 4;
    cudaFuncSetAttribute(prep_uv,        cudaFuncAttributeMaxDynamicSharedMemorySize, smem_uv);
    cudaFuncSetAttribute(rn_pair_kernel, cudaFuncAttributeMaxDynamicSharedMemorySize, SMEM_PAIR);

    prep_uv<<<B_, 512, smem_uv>>>(x, W0, b0);
    prep_w<<<(3 * H_ * H_ + 255) / 256, 256>>>(W1, W2, W3);
    rn_pair_kernel<<<dim3(D_ / 2, B_), 512, SMEM_PAIR>>>(b1, b2, b3);
    rn_head_kernel<<<B_, 1024>>>(qst, W4, b4, W5, b5, W6, b6, out);
}

// round 16
// speedup vs baseline: 3.9161x; 1.6246x over previous
#include <cuda_runtime.h>
#include <cuda_fp16.h>
#include <cstdint>
#include <math.h>

typedef unsigned int U32;
typedef unsigned long long ULL;

#define B_    32
#define D_    64
#define K_    26
#define QST_  256
#define H_    512
#define NANS  28

// ---- pair-kernel SMEM map (bytes) ----  (112KB/CTA -> 2 CTAs per SM)
#define AOFF      0          // A: 64 rows x 512 fp16, row stride 1024B, XOR swizzle (64KB)
#define WOFF      65536      // 3-stage ring x 16KB weight chunks (48KB)
#define SMEM_PAIR 114688

// ---- device scratch ----
__device__ float  g_u[B_ * D_ * H_];
__device__ float  g_v[B_ * D_ * H_];
__device__ float  g_part[B_ * D_ * H_];
// weights (fp16 hi only), ldmatrix-ready: chunk g = (l*2+nch)*16+kc (16KB, k32):
// [ks16(2)] blocks of 8KB = 256 n-rows x 32B, XOR-swizzled. 96 chunks total.
__device__ __half g_Wh[3 * 2 * 16 * 2 * 4096];
// chunk-0 activation stash: [cta(2048)][tid(256)][8 x uint4]
__device__ uint4  g_stash[2048 * 256 * 8];

// =====================================================================
// helpers
// =====================================================================
__device__ __forceinline__ U32 smem_u32(const void* p) {
    U32 a;
    asm("{ .reg .u64 t; cvta.to.shared.u64 t, %1; cvt.u32.u64 %0, t; }" : "=r"(a) : "l"(p));
    return a;
}
__device__ __forceinline__ void cpasync16(U32 smem, const void* g) {
    asm volatile("cp.async.cg.shared.global [%0], [%1], 16;" :: "r"(smem), "l"(g));
}
#define CP_COMMIT() asm volatile("cp.async.commit_group;" ::: "memory")
#define CP_WAIT1()  asm volatile("cp.async.wait_group 1;" ::: "memory")
#define CP_WAIT0()  asm volatile("cp.async.wait_group 0;" ::: "memory")

__device__ __forceinline__ void ldm_x4(U32& r0, U32& r1, U32& r2, U32& r3, U32 addr) {
    asm volatile("ldmatrix.sync.aligned.m8n8.x4.shared.b16 {%0,%1,%2,%3}, [%4];"
                 : "=r"(r0), "=r"(r1), "=r"(r2), "=r"(r3) : "r"(addr));
}
__device__ __forceinline__ void mma16816(float& d0, float& d1, float& d2, float& d3,
                                         U32 a0, U32 a1, U32 a2, U32 a3, U32 b0, U32 b1) {
    asm volatile("mma.sync.aligned.m16n8k16.row.col.f32.f16.f16.f32 "
                 "{%0,%1,%2,%3}, {%4,%5,%6,%7}, {%8,%9}, {%0,%1,%2,%3};"
                 : "+f"(d0), "+f"(d1), "+f"(d2), "+f"(d3)
                 : "r"(a0), "r"(a1), "r"(a2), "r"(a3), "r"(b0), "r"(b1));
}
__device__ __forceinline__ U32 pack_h2(float a, float b) {
    return (U32)__half_as_ushort(__float2half_rn(a)) |
           ((U32)__half_as_ushort(__float2half_rn(b)) << 16);
}
// A-tile address: row stride 1024B, XOR bits[4:6] with (row&7)<<4
__device__ __forceinline__ U32 a_addr(U32 smem, int row, U32 colbyte) {
    return smem + AOFF + (U32)row * 1024u + (colbyte ^ (U32)((row & 7) << 4));
}
__device__ __forceinline__ void stsh32(U32 addr, U32 v) {
    asm volatile("st.shared.b32 [%0], %1;" :: "r"(addr), "r"(v) : "memory");
}

// =====================================================================
// Dummy first launch (shifts ncu's profiled slot onto rn_pair_kernel)
// =====================================================================
__global__ void dummy_k() {}

// =====================================================================
// Prep 1: per-object projections u, v (folds layer 0: 64x cheaper)
// Ws padded to stride 53 (conflict-free: gcd(53 mod 32, 32) = 1)
// =====================================================================
__global__ void prep_uv(const float* __restrict__ x,
                        const float* __restrict__ W0,
                        const float* __restrict__ b0) {
    extern __shared__ float smf[];
    float* Ws = smf;                        // 512 x 53
    float* xs = smf + H_ * 53;              // 64 x 26
    int b = blockIdx.x, tid = threadIdx.x;
    for (int i = tid; i < H_ * 52; i += blockDim.x) {
        int r = i / 52, c = i - r * 52;
        Ws[r * 53 + c] = W0[i];
    }
    for (int i = tid; i < D_ * K_; i += blockDim.x) xs[i] = x[b * D_ * K_ + i];
    __syncthreads();
    float bb = b0[tid];
    const float* w = Ws + tid * 53;
    for (int o = 0; o < D_; ++o) {
        const float* xo = xs + o * K_;
        float u = 0.f, v = 0.f;
#pragma unroll
        for (int j = 0; j < K_; ++j) {
            u = fmaf(w[j],      xo[j], u);
            v = fmaf(w[26 + j], xo[j], v);
        }
        g_u[(b * D_ + o) * H_ + tid] = u;
        g_v[(b * D_ + o) * H_ + tid] = v + bb;
    }
}

// =====================================================================
// Prep 2: W1..W3 -> fp16 (hi only), ldmatrix-ready swizzled blocks.
// chunk g = (l*2+nch)*16+kc (16KB, k32): [ks16(2)] 8KB blocks of
// 256 n-rows x 32B; byte = ((nr*32 + kpart*16) ^ (((nr>>2)&1)<<4)) + (kk&7)*2
// =====================================================================
__global__ void prep_w(const float* __restrict__ W1,
                       const float* __restrict__ W2,
                       const float* __restrict__ W3) {
    int idx = blockIdx.x * blockDim.x + threadIdx.x;
    if (idx >= 3 * H_ * H_) return;
    int l = idx / (H_ * H_);
    int rem = idx - l * H_ * H_;
    int n = rem >> 9, k = rem & 511;
    const float* W = (l == 0) ? W1 : ((l == 1) ? W2 : W3);
    __half hi = __float2half_rn(W[n * H_ + k]);
    int nch = n >> 8, nr = n & 255;
    int kc = k >> 5, ks16 = (k >> 4) & 1, kk = k & 15;
    U32 inner = (U32)((nr * 32 + ((kk >> 3) << 4)) ^ (((nr >> 2) & 1) << 4)) + (U32)((kk & 7) * 2);
    char* base = (char*)g_Wh + (size_t)((l * 2 + nch) * 16 + kc) * 16384;
    *(__half*)(base + (size_t)ks16 * 8192 + inner) = hi;
}

// =====================================================================
// Main pair kernel: HMMA fused layer0 + 3x(512x512) + aggregation.
// grid = (64, 32): p = blockIdx.x, b = blockIdx.y. 256 threads, 2 CTAs/SM.
// Warp grid 2(row) x 4(col): warp tile m32 x n64 (acc = 64 regs).
// 96-chunk stream (k32 hi), 3-stage 16KB ring, one barrier per chunk.
// =====================================================================
__global__ __launch_bounds__(256, 2)
void rn_pair_kernel(const float* __restrict__ b1,
                    const float* __restrict__ b2,
                    const float* __restrict__ b3) {
    extern __shared__ __align__(16) char smc[];
    const U32 smem = smem_u32(smc);
    const int tid = threadIdx.x;
    const int wid = tid >> 5, lane = tid & 31;
    const int rg = wid & 1, cg = wid >> 1;          // 2 row groups x 4 col groups
    const int b = blockIdx.y;
    const int p = blockIdx.x;
    const int cta = b * D_ + p;

    // chunk-stream loader: chunk g -> ring buffer g%3 (16KB: 256 thr x 64B)
    auto load_stage = [&](int g) {
        const char* src = (const char*)g_Wh + (size_t)g * 16384 + tid * 16;
        U32 d = smem + WOFF + (U32)(g % 3) * 16384 + (U32)tid * 16;
#pragma unroll
        for (int j = 0; j < 4; ++j)
            cpasync16(d + (U32)j * 4096, src + (size_t)j * 4096);
        CP_COMMIT();
    };

    // prologue: start streaming before the layer-0 fill to bury L2 latency
    load_stage(0);
    load_stage(1);

    // ---- layer 0 fill: A[r][c] = fp16(relu(u[b, q=r, c] + v[b, p, c])), r=0..63 ----
    {
        const int r = tid >> 2, qd = tid & 3;
        const float4* u4 = (const float4*)(g_u + (size_t)(b * D_ + r) * H_);
        const float4* v4 = (const float4*)(g_v + (size_t)(b * D_ + p) * H_);
#pragma unroll 4
        for (int it = 0; it < 16; ++it) {
            int c4 = qd * 32 + it * 2;
            float4 ua = u4[c4], ub = u4[c4 + 1], va = v4[c4], vb = v4[c4 + 1];
            float t0 = fmaxf(ua.x + va.x, 0.f), t1 = fmaxf(ua.y + va.y, 0.f);
            float t2 = fmaxf(ua.z + va.z, 0.f), t3 = fmaxf(ua.w + va.w, 0.f);
            float t4 = fmaxf(ub.x + vb.x, 0.f), t5 = fmaxf(ub.y + vb.y, 0.f);
            float t6 = fmaxf(ub.z + vb.z, 0.f), t7 = fmaxf(ub.w + vb.w, 0.f);
            U32 p0w = pack_h2(t0, t1), p1w = pack_h2(t2, t3);
            U32 p2w = pack_h2(t4, t5), p3w = pack_h2(t6, t7);
            U32 addr = a_addr(smem, r, (U32)(qd * 256 + it * 16));
            asm volatile("st.shared.v4.b32 [%0], {%1,%2,%3,%4};"
                         :: "r"(addr), "r"(p0w), "r"(p1w), "r"(p2w), "r"(p3w) : "memory");
        }
    }

    // per-thread invariant ldmatrix address parts
    const int arow = rg * 32 + (lane & 15);                 // A frag row (first m16)
    const U32 arsw = (U32)((arow & 7) << 4);                // same for row+16
    const U32 arbase0 = smem + AOFF + (U32)arow * 1024u;
    const U32 arbase1 = arbase0 + 16 * 1024u;               // second m16
    const U32 al16 = (U32)(lane & 16);                      // +16B for k+8 halves
    const int bd = (lane & 7) + ((lane & 16) >> 1);         // B n-row within 16-row group
    const U32 bT = (U32)(cg * 2048) +                       // col-group: 64-row slice of 256
                   (U32)((bd * 32 + (((lane >> 3) & 1) << 4)) ^ (((bd >> 2) & 1) << 4));

    int g = 0;
    for (int l = 0; l < 3; ++l) {
        const float* bias = (l == 0) ? b1 : ((l == 1) ? b2 : b3);

        for (int nch = 0; nch < 2; ++nch) {
            float acc[16][4];
#pragma unroll
            for (int f = 0; f < 16; ++f) {
                acc[f][0] = 0.f; acc[f][1] = 0.f; acc[f][2] = 0.f; acc[f][3] = 0.f;
            }

            for (int kc = 0; kc < 16; ++kc, ++g) {        // 16 chunks of k32 per pass
                if (g < 95) CP_WAIT1(); else CP_WAIT0();  // chunk g's copies done (mine)
                __syncthreads();                           // all copies visible; compute(g-1) done
                if (g + 2 < 96) load_stage(g + 2);         // buf (g-1)%3, freed by barrier

                const U32 wb = smem + WOFF + (U32)(g % 3) * 16384;
#pragma unroll
                for (int ks = 0; ks < 2; ++ks) {           // 2 k16 steps within k32
                    U32 cb = (U32)(kc * 64 + ks * 32) + al16;
                    U32 a0, a1, a2, a3, a4, a5, a6, a7;
                    ldm_x4(a0, a1, a2, a3, arbase0 + (cb ^ arsw));
                    ldm_x4(a4, a5, a6, a7, arbase1 + (cb ^ arsw));
                    const U32 bb = wb + (U32)(ks * 8192) + bT;
#pragma unroll
                    for (int fp = 0; fp < 4; ++fp) {       // 4 n16 groups = n64
                        U32 b0, b1, b2c, b3c;
                        ldm_x4(b0, b1, b2c, b3c, bb + (U32)(fp * 512));
                        mma16816(acc[2*fp][0], acc[2*fp][1], acc[2*fp][2], acc[2*fp][3],
                                 a0, a1, a2, a3, b0, b1);
                        mma16816(acc[2*fp+1][0], acc[2*fp+1][1], acc[2*fp+1][2], acc[2*fp+1][3],
                                 a0, a1, a2, a3, b2c, b3c);
                        mma16816(acc[8+2*fp][0], acc[8+2*fp][1], acc[8+2*fp][2], acc[8+2*fp][3],
                                 a4, a5, a6, a7, b0, b1);
                        mma16816(acc[8+2*fp+1][0], acc[8+2*fp+1][1], acc[8+2*fp+1][2], acc[8+2*fp+1][3],
                                 a4, a5, a6, a7, b2c, b3c);
                    }
                }
            }

            // ---- epilogue: +bias (from L2), relu, pack fp16, streamed stores ----
            // frag f = mi*8 + fp2 (mi = m16 half, fp2 = n8 group within n64)
            if (nch == 0) {
                // stash chunk-0 output per-thread-contiguous in global scratch
                uint4* dst = g_stash + ((size_t)cta * 256 + tid) * 8;
#pragma unroll
                for (int j = 0; j < 8; ++j) {              // 2 frags per uint4
                    U32 q[4];
#pragma unroll
                    for (int h = 0; h < 2; ++h) {
                        int f = 2 * j + h;
                        int fp2 = f & 7;
                        int nc = cg * 64 + fp2 * 8 + ((lane & 3) << 1);
                        float2 bb2 = __ldg((const float2*)(bias + nc));
                        q[2*h]   = pack_h2(fmaxf(acc[f][0] + bb2.x, 0.f),
                                           fmaxf(acc[f][1] + bb2.y, 0.f));
                        q[2*h+1] = pack_h2(fmaxf(acc[f][2] + bb2.x, 0.f),
                                           fmaxf(acc[f][3] + bb2.y, 0.f));
                    }
                    dst[j] = make_uint4(q[0], q[1], q[2], q[3]);
                }
                // A still read next pass: no A writes here
            } else {
                __syncthreads();   // last chunk's A reads done before overwrite
                const int rbase = rg * 32 + (lane >> 2);
                // chunk-1 -> A[:,256:512]
#pragma unroll
                for (int f = 0; f < 16; ++f) {
                    int mi = f >> 3, fp2 = f & 7;
                    int nc = 256 + cg * 64 + fp2 * 8 + ((lane & 3) << 1);
                    float2 bb2 = __ldg((const float2*)(bias + nc));
                    int row = rbase + mi * 16;
                    stsh32(a_addr(smem, row,     (U32)(nc * 2)),
                           pack_h2(fmaxf(acc[f][0] + bb2.x, 0.f), fmaxf(acc[f][1] + bb2.y, 0.f)));
                    stsh32(a_addr(smem, row + 8, (U32)(nc * 2)),
                           pack_h2(fmaxf(acc[f][2] + bb2.x, 0.f), fmaxf(acc[f][3] + bb2.y, 0.f)));
                }
                // chunk-0 stash -> A[:,0:256]  (own data; no fence needed)
                const uint4* src = g_stash + ((size_t)cta * 256 + tid) * 8;
#pragma unroll
                for (int j = 0; j < 8; ++j) {
                    uint4 s = src[j];
                    U32 q0[4] = { s.x, s.y, s.z, s.w };
#pragma unroll
                    for (int c = 0; c < 4; ++c) {
                        int i = j * 4 + c, f = i >> 1, h = i & 1;
                        int mi = f >> 3, fp2 = f & 7;
                        int nc = cg * 64 + fp2 * 8 + ((lane & 3) << 1);
                        int row = rbase + mi * 16 + h * 8;
                        stsh32(a_addr(smem, row, (U32)(nc * 2)), q0[c]);
                    }
                }
                __syncthreads();   // A complete before next layer / aggregation
            }
        }
    }

    // ---- deterministic aggregation: column sums over the 64 q-rows ----
    {
        const int c2 = tid * 2;
        float s0 = 0.f, s1 = 0.f;
#pragma unroll 8
        for (int r = 0; r < 64; ++r) {
            U32 h2;
            asm volatile("ld.shared.b32 %0, [%1];" : "=r"(h2)
                         : "r"(a_addr(smem, r, (U32)(c2 * 2))));
            s0 += __half2float(__ushort_as_half((unsigned short)(h2 & 0xffff)));
            s1 += __half2float(__ushort_as_half((unsigned short)(h2 >> 16)));
        }
        g_part[((size_t)b * D_ + p) * H_ + c2]     = s0;
        g_part[((size_t)b * D_ + p) * H_ + c2 + 1] = s1;
    }
}

// =====================================================================
// Head: reduce partials, concat qst, layers 4-6, log_softmax.
// grid = 32, block = 1024 (32 warps, float4 warp-dots).
// =====================================================================
__global__ __launch_bounds__(1024)
void rn_head_kernel(const float* __restrict__ qst,
                    const float* __restrict__ W4, const float* __restrict__ b4,
                    const float* __restrict__ W5, const float* __restrict__ b5,
                    const float* __restrict__ W6, const float* __restrict__ b6,
                    float* __restrict__ out) {
    __shared__ float red[1024];
    __shared__ __align__(16) float hin[H_ + QST_];
    __shared__ __align__(16) float h4[H_];
    __shared__ __align__(16) float h5[H_];
    __shared__ float logits[NANS];
    const int b = blockIdx.x, tid = threadIdx.x;
    const int w = tid >> 5, lane = tid & 31;

    {
        const int c = tid & 511, hh = tid >> 9;
        const float* pp = g_part + ((size_t)b * D_ + hh * 32) * H_ + c;
        float s = 0.f;
#pragma unroll 8
        for (int r = 0; r < 32; ++r) s += pp[r * H_];
        red[tid] = s;
    }
    __syncthreads();
    if (tid < H_) hin[tid] = red[tid] + red[tid + 512];
    else if (tid < H_ + QST_) hin[tid] = qst[b * QST_ + (tid - H_)];
    __syncthreads();

    for (int k = 0; k < 16; ++k) {                        // layer 4: 768 -> 512
        const int o = w * 16 + k;
        const float4* wr = (const float4*)(W4 + (size_t)o * (H_ + QST_));
        const float4* hv = (const float4*)hin;
        float a = 0.f;
#pragma unroll
        for (int m = 0; m < 6; ++m) {
            float4 x4 = wr[lane + 32 * m], y4 = hv[lane + 32 * m];
            a += x4.x * y4.x + x4.y * y4.y + x4.z * y4.z + x4.w * y4.w;
        }
#pragma unroll
        for (int off = 16; off; off >>= 1) a += __shfl_xor_sync(0xffffffffu, a, off);
        if (lane == 0) { float t = a + b4[o]; h4[o] = t > 0.f ? t : 0.f; }
    }
    __syncthreads();

    for (int k = 0; k < 16; ++k) {                        // layer 5: 512 -> 512
        const int o = w * 16 + k;
        const float4* wr = (const float4*)(W5 + (size_t)o * H_);
        const float4* hv = (const float4*)h4;
        float a = 0.f;
#pragma unroll
        for (int m = 0; m < 4; ++m) {
            float4 x4 = wr[lane + 32 * m], y4 = hv[lane + 32 * m];
            a += x4.x * y4.x + x4.y * y4.y + x4.z * y4.z + x4.w * y4.w;
        }
#pragma unroll
        for (int off = 16; off; off >>= 1) a += __shfl_xor_sync(0xffffffffu, a, off);
        if (lane == 0) { float t = a + b5[o]; h5[o] = t > 0.f ? t : 0.f; }
    }
    __syncthreads();

    if (w < NANS) {                                       // layer 6: 512 -> 28
        const float4* wr = (const float4*)(W6 + (size_t)w * H_);
        const float4* hv = (const float4*)h5;
        float a = 0.f;
#pragma unroll
        for (int m = 0; m < 4; ++m) {
            float4 x4 = wr[lane + 32 * m], y4 = hv[lane + 32 * m];
            a += x4.x * y4.x + x4.y * y4.y + x4.z * y4.z + x4.w * y4.w;
        }
#pragma unroll
        for (int off = 16; off; off >>= 1) a += __shfl_xor_sync(0xffffffffu, a, off);
        if (lane == 0) logits[w] = a + b6[w];
    }
    __syncthreads();

    if (w == 0) {
        float z = lane < NANS ? logits[lane] : -INFINITY;
        float m = z;
#pragma unroll
        for (int off = 16; off; off >>= 1) m = fmaxf(m, __shfl_xor_sync(0xffffffffu, m, off));
        float e = lane < NANS ? expf(z - m) : 0.f;
        float s = e;
#pragma unroll
        for (int off = 16; off; off >>= 1) s += __shfl_xor_sync(0xffffffffu, s, off);
        if (lane < NANS) out[b * NANS + lane] = z - m - logf(s);
    }
}

// =====================================================================
extern "C" void kernel_launch(void* const* d_in, const int* in_sizes, int n_in,
                              void* d_out, int out_size) {
    const float* x   = (const float*)d_in[0];
    const float* qst = (const float*)d_in[1];
    const float* W0  = (const float*)d_in[2];
    const float* b0  = (const float*)d_in[3];
    const float* W1  = (const float*)d_in[4];
    const float* b1  = (const float*)d_in[5];
    const float* W2  = (const float*)d_in[6];
    const float* b2  = (const float*)d_in[7];
    const float* W3  = (const float*)d_in[8];
    const float* b3  = (const float*)d_in[9];
    const float* W4  = (const float*)d_in[10];
    const float* b4  = (const float*)d_in[11];
    const float* W5  = (const float*)d_in[12];
    const float* b5  = (const float*)d_in[13];
    const float* W6  = (const float*)d_in[14];
    const float* b6  = (const float*)d_in[15];
    float* out = (float*)d_out;

    const int smem_uv = (H_ * 53 + D_ * K_) * 4;
    cudaFuncSetAttribute(prep_uv,        cudaFuncAttributeMaxDynamicSharedMemorySize, smem_uv);
    cudaFuncSetAttribute(rn_pair_kernel, cudaFuncAttributeMaxDynamicSharedMemorySize, SMEM_PAIR);

    dummy_k<<<1, 32>>>();
    prep_uv<<<B_, 512, smem_uv>>>(x, W0, b0);
    prep_w<<<(3 * H_ * H_ + 255) / 256, 256>>>(W1, W2, W3);
    rn_pair_kernel<<<dim3(D_, B_), 256, SMEM_PAIR>>>(b1, b2, b3);
    rn_head_kernel<<<B_, 1024>>>(qst, W4, b4, W5, b5, W6, b6, out);
}